// round 13
// baseline (speedup 1.0000x reference)
#include <cuda_runtime.h>
#include <cuda_bf16.h>
#include <cstdint>
#include <math.h>

#define Bx 8
#define Ntok 512
#define Dm 768
#define Hh 12
#define HD 64
#define NL 6
#define DFF 3072
#define Mrows (Bx * Ntok)      // 4096
#define Tlen 8192
#define PATCH 16

// ---------------- scratch (device globals; no allocation) ----------------
__device__ float g_z[Mrows * Dm];
__device__ float g_h[Mrows * Dm];
__device__ float g_qkv[Mrows * 3 * Dm];
__device__ float g_enc[Bx * Dm];

__device__ __nv_bfloat16 g_hh[Mrows * Dm],  g_hl[Mrows * Dm];
__device__ __nv_bfloat16 g_oh[Mrows * Dm],  g_ol[Mrows * Dm];
__device__ __nv_bfloat16 g_fh[Mrows * DFF], g_fl[Mrows * DFF];

#define NQKV (NL * 3 * Dm * Dm)
#define NOUT (NL * Dm * Dm)
#define NFC1 (NL * DFF * Dm)
#define NFC2 (NL * Dm * DFF)
__device__ __nv_bfloat16 g_wqkv_h[NQKV], g_wqkv_l[NQKV];
__device__ __nv_bfloat16 g_wout_h[NOUT], g_wout_l[NOUT];
__device__ __nv_bfloat16 g_wfc1_h[NFC1], g_wfc1_l[NFC1];
__device__ __nv_bfloat16 g_wfc2_h[NFC2], g_wfc2_l[NFC2];

// ---------------- helpers ----------------
__device__ __forceinline__ void split_bf16(float x, __nv_bfloat16& h, __nv_bfloat16& l) {
    h = __float2bfloat16_rn(x);
    l = __float2bfloat16_rn(x - __bfloat162float(h));
}
__device__ __forceinline__ uint32_t sw128(uint32_t o) { return o ^ ((o >> 3) & 0x70); }
__device__ __forceinline__ uint32_t smem_u32(const void* p) {
    return (uint32_t)__cvta_generic_to_shared(p);
}
__device__ __forceinline__ void cp16(uint32_t dst, const void* src) {
    asm volatile("cp.async.cg.shared.global [%0], [%1], 16;" :: "r"(dst), "l"(src));
}
__device__ __forceinline__ void ldmx4(uint32_t* r, uint32_t addr) {
    asm volatile("ldmatrix.sync.aligned.m8n8.x4.shared.b16 {%0,%1,%2,%3}, [%4];"
                 : "=r"(r[0]), "=r"(r[1]), "=r"(r[2]), "=r"(r[3]) : "r"(addr));
}
__device__ __forceinline__ void mma16(float* c, const uint32_t* a, const uint32_t* b) {
    asm volatile("mma.sync.aligned.m16n8k16.row.col.f32.bf16.bf16.f32 "
                 "{%0,%1,%2,%3}, {%4,%5,%6,%7}, {%8,%9}, {%0,%1,%2,%3};"
                 : "+f"(c[0]), "+f"(c[1]), "+f"(c[2]), "+f"(c[3])
                 : "r"(a[0]), "r"(a[1]), "r"(a[2]), "r"(a[3]),
                   "r"(b[0]), "r"(b[1]));
}

// ---------------- weight split (vectorized x4) ----------------
__global__ void split_kernel(const float* __restrict__ src,
                             __nv_bfloat16* __restrict__ hi,
                             __nv_bfloat16* __restrict__ lo, int n) {
    int i = (blockIdx.x * 256 + threadIdx.x) * 4;
    if (i >= n) return;
    float4 v = *(const float4*)(src + i);
    __nv_bfloat16 h0, l0, h1, l1, h2, l2, h3, l3;
    split_bf16(v.x, h0, l0); split_bf16(v.y, h1, l1);
    split_bf16(v.z, h2, l2); split_bf16(v.w, h3, l3);
    ushort4 hv, lv;
    hv.x = *(uint16_t*)&h0; hv.y = *(uint16_t*)&h1; hv.z = *(uint16_t*)&h2; hv.w = *(uint16_t*)&h3;
    lv.x = *(uint16_t*)&l0; lv.y = *(uint16_t*)&l1; lv.z = *(uint16_t*)&l2; lv.w = *(uint16_t*)&l3;
    *(ushort4*)(hi + i) = hv;
    *(ushort4*)(lo + i) = lv;
}

// ---------------- patch embed + positional ----------------
__global__ void patch_embed_kernel(const float* __restrict__ x,
                                   const float* __restrict__ pp_w,
                                   const float* __restrict__ pp_b,
                                   const float* __restrict__ pe,
                                   float* __restrict__ z) {
    int idx = blockIdx.x * blockDim.x + threadIdx.x;
    if (idx >= Mrows * Dm) return;
    int row = idx / Dm;
    int d   = idx - row * Dm;
    int b = row >> 9;
    int n = row & 511;
    const float* xr = x + (size_t)b * Tlen + n * PATCH;
    const float* wr = pp_w + (size_t)d * PATCH;
    float s = pp_b[d];
#pragma unroll
    for (int p = 0; p < PATCH; ++p) s += xr[p] * wr[p];
    z[idx] = s + pe[(size_t)n * Dm + d];
}

// ---------------- LayerNorm: warp per row ----------------
template<int OUT>
__global__ __launch_bounds__(256)
void ln_kernel(const float* __restrict__ X,
               const float* __restrict__ gam,
               const float* __restrict__ bet,
               float* __restrict__ Yf,
               __nv_bfloat16* __restrict__ Yh,
               __nv_bfloat16* __restrict__ Yl) {
    const int warp = threadIdx.x >> 5, lane = threadIdx.x & 31;
    const int row = blockIdx.x * 8 + warp;
    const float4* xr = (const float4*)(X + (size_t)row * Dm);
    float4 v[6];
    float s = 0.f;
#pragma unroll
    for (int k = 0; k < 6; ++k) {
        v[k] = xr[lane + 32 * k];
        s += v[k].x + v[k].y + v[k].z + v[k].w;
    }
#pragma unroll
    for (int off = 16; off > 0; off >>= 1) s += __shfl_xor_sync(0xFFFFFFFFu, s, off);
    const float mean = s * (1.0f / Dm);
    float var = 0.f;
#pragma unroll
    for (int k = 0; k < 6; ++k) {
        float a = v[k].x - mean, b = v[k].y - mean, c = v[k].z - mean, d = v[k].w - mean;
        var += a * a + b * b + c * c + d * d;
    }
#pragma unroll
    for (int off = 16; off > 0; off >>= 1) var += __shfl_xor_sync(0xFFFFFFFFu, var, off);
    const float rstd = rsqrtf(var * (1.0f / Dm) + 1e-5f);

#pragma unroll
    for (int k = 0; k < 6; ++k) {
        int j4 = lane + 32 * k;
        float4 g = ((const float4*)gam)[j4];
        float4 b = ((const float4*)bet)[j4];
        float y0 = (v[k].x - mean) * rstd * g.x + b.x;
        float y1 = (v[k].y - mean) * rstd * g.y + b.y;
        float y2 = (v[k].z - mean) * rstd * g.z + b.z;
        float y3 = (v[k].w - mean) * rstd * g.w + b.w;
        if (OUT == 0) {
            ((float4*)(Yf + (size_t)row * Dm))[j4] = make_float4(y0, y1, y2, y3);
        } else {
            __nv_bfloat16 h0, l0, h1, l1, h2, l2, h3, l3;
            split_bf16(y0, h0, l0); split_bf16(y1, h1, l1);
            split_bf16(y2, h2, l2); split_bf16(y3, h3, l3);
            ushort4 hv, lv;
            hv.x = *(uint16_t*)&h0; hv.y = *(uint16_t*)&h1;
            hv.z = *(uint16_t*)&h2; hv.w = *(uint16_t*)&h3;
            lv.x = *(uint16_t*)&l0; lv.y = *(uint16_t*)&l1;
            lv.z = *(uint16_t*)&l2; lv.w = *(uint16_t*)&l3;
            ((ushort4*)(Yh + (size_t)row * Dm))[j4] = hv;
            ((ushort4*)(Yl + (size_t)row * Dm))[j4] = lv;
        }
    }
}

// ---------------- bf16x3 mma.sync GEMM, KTILE=64, 3 stages (round-8 best) ----------------
#define KTILE 64
#define ST_OP 16384
#define STG (4 * ST_OP)
#define NSTAGE 3
#define GEMM_SMEM (NSTAGE * STG + 1024)

template<int EPI>
__global__ __launch_bounds__(256, 1)
void wgemm(const __nv_bfloat16* __restrict__ Ah, const __nv_bfloat16* __restrict__ Al,
           const __nv_bfloat16* __restrict__ Wh, const __nv_bfloat16* __restrict__ Wl,
           const float* __restrict__ Res, float* __restrict__ Cf,
           __nv_bfloat16* __restrict__ Chi, __nv_bfloat16* __restrict__ Clo,
           int Nn, int K) {
    extern __shared__ char dyn_smem[];
    const int tid = threadIdx.x, lane = tid & 31, wid = tid >> 5;
    const int warpM = wid & 1, warpN = wid >> 1;
    uint32_t raw = smem_u32(dyn_smem);
    uint32_t sb0 = (raw + 1023u) & ~1023u;

    const int mBase = blockIdx.y * 128, nBase = blockIdx.x * 128;
    const int KT = K >> 6;

    uint32_t swl[4];
    const __nv_bfloat16 *pAh[4], *pAl[4], *pWh[4], *pWl[4];
#pragma unroll
    for (int i = 0; i < 4; ++i) {
        int q = tid + i * 256;
        int row = q >> 3, c = q & 7;
        swl[i] = sw128((uint32_t)(row * 128 + c * 16));
        size_t ga = (size_t)(mBase + row) * K + c * 8;
        size_t gw = (size_t)(nBase + row) * K + c * 8;
        pAh[i] = Ah + ga; pAl[i] = Al + ga;
        pWh[i] = Wh + gw; pWl[i] = Wl + gw;
    }

    float acc[4][4][4];
#pragma unroll
    for (int i = 0; i < 4; ++i)
#pragma unroll
        for (int j = 0; j < 4; ++j)
#pragma unroll
            for (int q = 0; q < 4; ++q) acc[i][j][q] = 0.f;

#define LOADSTG(kt)                                                              \
    do {                                                                         \
        const int kofs_ = (kt) * KTILE;                                          \
        const uint32_t sb_ = sb0 + ((kt) % NSTAGE) * STG;                        \
        _Pragma("unroll")                                                        \
        for (int i_ = 0; i_ < 4; ++i_) {                                         \
            cp16(sb_ + swl[i_],              pAh[i_] + kofs_);                   \
            cp16(sb_ + ST_OP + swl[i_],      pAl[i_] + kofs_);                   \
            cp16(sb_ + 2 * ST_OP + swl[i_],  pWh[i_] + kofs_);                   \
            cp16(sb_ + 3 * ST_OP + swl[i_],  pWl[i_] + kofs_);                   \
        }                                                                        \
        asm volatile("cp.async.commit_group;" ::: "memory");                     \
    } while (0)

    LOADSTG(0);
    LOADSTG(1);

    const int arow = warpM * 64 + (lane & 15);
    const int akb  = (lane >> 4) << 4;
    const int bprow = warpN * 32 + ((lane >> 4) & 1) * 8 + (lane & 7);
    const int bpkb  = ((lane >> 3) & 1) << 4;

    for (int kt = 0; kt < KT; ++kt) {
        if (kt + 1 < KT) {
            asm volatile("cp.async.wait_group 1;" ::: "memory");
        } else {
            asm volatile("cp.async.wait_group 0;" ::: "memory");
        }
        __syncthreads();
        if (kt + 2 < KT) LOADSTG(kt + 2);

        const uint32_t A0 = sb0 + (kt % NSTAGE) * STG;
        const uint32_t W0 = A0 + 2 * ST_OP;

#pragma unroll
        for (int kc = 0; kc < 4; ++kc) {
            uint32_t ah[4][4], al[4][4];
#pragma unroll
            for (int i = 0; i < 4; ++i) {
                uint32_t off = sw128((uint32_t)((arow + i * 16) * 128 + kc * 32 + akb));
                ldmx4(ah[i], A0 + off);
                ldmx4(al[i], A0 + ST_OP + off);
            }
            uint32_t bh[4][2], bl[4][2];
#pragma unroll
            for (int jp = 0; jp < 2; ++jp) {
                uint32_t off = sw128((uint32_t)((bprow + jp * 16) * 128 + kc * 32 + bpkb));
                uint32_t r[4];
                ldmx4(r, W0 + off);
                bh[2 * jp][0] = r[0]; bh[2 * jp][1] = r[1];
                bh[2 * jp + 1][0] = r[2]; bh[2 * jp + 1][1] = r[3];
                ldmx4(r, W0 + ST_OP + off);
                bl[2 * jp][0] = r[0]; bl[2 * jp][1] = r[1];
                bl[2 * jp + 1][0] = r[2]; bl[2 * jp + 1][1] = r[3];
            }
#pragma unroll
            for (int i = 0; i < 4; ++i)
#pragma unroll
                for (int j = 0; j < 4; ++j) {
                    mma16(acc[i][j], ah[i], bh[j]);
                    mma16(acc[i][j], ah[i], bl[j]);
                    mma16(acc[i][j], al[i], bh[j]);
                }
        }
    }

    const int erow = warpM * 64 + (lane >> 2);
    const int ecol = warpN * 32 + (lane & 3) * 2;
#pragma unroll
    for (int i = 0; i < 4; ++i) {
        int row0 = mBase + erow + i * 16;
#pragma unroll
        for (int j = 0; j < 4; ++j) {
            int col = nBase + ecol + j * 8;
            size_t g0 = (size_t)row0 * Nn + col;
            size_t g1 = g0 + (size_t)8 * Nn;
            float v0 = acc[i][j][0], v1 = acc[i][j][1];
            float v2 = acc[i][j][2], v3 = acc[i][j][3];
            if (EPI == 0) {
                *(float2*)(Cf + g0) = make_float2(v0, v1);
                *(float2*)(Cf + g1) = make_float2(v2, v3);
            } else if (EPI == 1) {
                float2 r0 = *(const float2*)(Res + g0);
                float2 r1 = *(const float2*)(Res + g1);
                *(float2*)(Cf + g0) = make_float2(v0 + r0.x, v1 + r0.y);
                *(float2*)(Cf + g1) = make_float2(v2 + r1.x, v3 + r1.y);
            } else {
                v0 = 0.5f * v0 * (1.0f + erff(v0 * 0.70710678118654752f));
                v1 = 0.5f * v1 * (1.0f + erff(v1 * 0.70710678118654752f));
                v2 = 0.5f * v2 * (1.0f + erff(v2 * 0.70710678118654752f));
                v3 = 0.5f * v3 * (1.0f + erff(v3 * 0.70710678118654752f));
                __nv_bfloat16 h0, l0, h1, l1, h2, l2, h3, l3;
                split_bf16(v0, h0, l0); split_bf16(v1, h1, l1);
                split_bf16(v2, h2, l2); split_bf16(v3, h3, l3);
                *(__nv_bfloat162*)(Chi + g0) = __nv_bfloat162(h0, h1);
                *(__nv_bfloat162*)(Clo + g0) = __nv_bfloat162(l0, l1);
                *(__nv_bfloat162*)(Chi + g1) = __nv_bfloat162(h2, h3);
                *(__nv_bfloat162*)(Clo + g1) = __nv_bfloat162(l2, l3);
            }
        }
    }
}

// ---------------- causal attention v5: 64 q/CTA, reg-prefetch, vectorized LDS ----------------
// strides: Ks/Qs/Ps = 66 (even -> float2-aligned, conflict-free), Vs = 68
#define ATT_KS   0
#define ATT_VS   (64 * 66)
#define ATT_QS   (ATT_VS + 64 * 68)
#define ATT_PS   (ATT_QS + 64 * 66)
#define ATT_SMEM ((ATT_PS + 64 * 66) * (int)sizeof(float))   // 68096 B

__global__ __launch_bounds__(256)
void attn_kernel(const float* __restrict__ qkv,
                 __nv_bfloat16* __restrict__ ohi, __nv_bfloat16* __restrict__ olo) {
    extern __shared__ float asm_[];
    float* Ks = asm_ + ATT_KS;
    float* Vs = asm_ + ATT_VS;
    float* Qs = asm_ + ATT_QS;
    float* Ps = asm_ + ATT_PS;
    const int b = blockIdx.z, h = blockIdx.y;
    const int qb = gridDim.x - 1 - blockIdx.x;     // heaviest first
    const int warp = threadIdx.x >> 5, lane = threadIdx.x & 31;
    const int tid = threadIdx.x;
    const int qBase = qb * 64;
    const int ql0 = warp * 8;

    const int mT = tid >> 4;            // row 0..15 (+16 per i)
    const int dcT = (tid & 15) * 4;     // column

    for (int i = tid; i < 1024; i += 256) {
        int q = i >> 4, dc = (i & 15) * 4;
        float4 v = *(const float4*)&qkv[((size_t)(b * Ntok + qBase + q)) * (3 * Dm) + h * HD + dc];
        Qs[q * 66 + dc + 0] = v.x; Qs[q * 66 + dc + 1] = v.y;
        Qs[q * 66 + dc + 2] = v.z; Qs[q * 66 + dc + 3] = v.w;
    }

    float4 kreg[4], vreg[4];
#define LOADCHUNK(c)                                                                     \
    do {                                                                                 \
        _Pragma("unroll")                                                                \
        for (int i_ = 0; i_ < 4; ++i_) {                                                 \
            int m_ = mT + i_ * 16;                                                       \
            size_t base_ = ((size_t)(b * Ntok + (c) * 64 + m_)) * (3 * Dm) + h * HD + dcT; \
            kreg[i_] = *(const float4*)&qkv[base_ + Dm];                                 \
            vreg[i_] = *(const float4*)&qkv[base_ + 2 * Dm];                             \
        }                                                                                \
    } while (0)

    LOADCHUNK(0);

    float accX[8], accY[8], Mx[8], Sum[8];
#pragma unroll
    for (int j = 0; j < 8; ++j) {
        accX[j] = 0.f; accY[j] = 0.f; Mx[j] = -INFINITY; Sum[j] = 0.f;
    }

    const int lastChunk = qb;

    for (int c = 0; c <= lastChunk; ++c) {
        __syncthreads();
#pragma unroll
        for (int i = 0; i < 4; ++i) {
            int m = mT + i * 16;
            Ks[m * 66 + dcT + 0] = kreg[i].x; Ks[m * 66 + dcT + 1] = kreg[i].y;
            Ks[m * 66 + dcT + 2] = kreg[i].z; Ks[m * 66 + dcT + 3] = kreg[i].w;
            Vs[m * 68 + dcT + 0] = vreg[i].x; Vs[m * 68 + dcT + 1] = vreg[i].y;
            Vs[m * 68 + dcT + 2] = vreg[i].z; Vs[m * 68 + dcT + 3] = vreg[i].w;
        }
        __syncthreads();
        if (c < lastChunk) LOADCHUNK(c + 1);

        {
            float s1[8], s2[8];
#pragma unroll
            for (int j = 0; j < 8; ++j) { s1[j] = 0.f; s2[j] = 0.f; }
#pragma unroll
            for (int dd = 0; dd < 32; ++dd) {
                float2 kd1 = *(const float2*)&Ks[lane * 66 + 2 * dd];
                float2 kd2 = *(const float2*)&Ks[(lane + 32) * 66 + 2 * dd];
#pragma unroll
                for (int j = 0; j < 8; ++j) {
                    float2 qd = *(const float2*)&Qs[(ql0 + j) * 66 + 2 * dd];
                    s1[j] = fmaf(qd.x, kd1.x, s1[j]);
                    s1[j] = fmaf(qd.y, kd1.y, s1[j]);
                    s2[j] = fmaf(qd.x, kd2.x, s2[j]);
                    s2[j] = fmaf(qd.y, kd2.y, s2[j]);
                }
            }
            const int k1 = c * 64 + lane, k2 = k1 + 32;
#pragma unroll
            for (int j = 0; j < 8; ++j) {
                const int l = qBase + ql0 + j;
                float a1 = s1[j] * 0.125f, a2 = s2[j] * 0.125f;
                if (k1 > l) a1 = -INFINITY;
                if (k2 > l) a2 = -INFINITY;
                float cm = fmaxf(a1, a2);
#pragma unroll
                for (int off = 16; off > 0; off >>= 1)
                    cm = fmaxf(cm, __shfl_xor_sync(0xFFFFFFFFu, cm, off));
                float newM = fmaxf(Mx[j], cm);
                float scaleOld = __expf(Mx[j] - newM);
                float p1 = (k1 > l) ? 0.f : __expf(a1 - newM);
                float p2 = (k2 > l) ? 0.f : __expf(a2 - newM);
                float rs = p1 + p2;
#pragma unroll
                for (int off = 16; off > 0; off >>= 1)
                    rs += __shfl_xor_sync(0xFFFFFFFFu, rs, off);
                Sum[j] = Sum[j] * scaleOld + rs;
                Mx[j] = newM;
                accX[j] *= scaleOld; accY[j] *= scaleOld;
                Ps[(ql0 + j) * 66 + lane] = p1;
                Ps[(ql0 + j) * 66 + lane + 32] = p2;
            }
            __syncwarp();
#pragma unroll 2
            for (int mm = 0; mm < 32; ++mm) {
                const int m0 = 2 * mm;
                float2 v0 = *(const float2*)&Vs[m0 * 68 + 2 * lane];
                float2 v1 = *(const float2*)&Vs[(m0 + 1) * 68 + 2 * lane];
#pragma unroll
                for (int j = 0; j < 8; ++j) {
                    float2 p = *(const float2*)&Ps[(ql0 + j) * 66 + m0];
                    accX[j] = fmaf(p.x, v0.x, accX[j]);
                    accY[j] = fmaf(p.x, v0.y, accY[j]);
                    accX[j] = fmaf(p.y, v1.x, accX[j]);
                    accY[j] = fmaf(p.y, v1.y, accY[j]);
                }
            }
            __syncwarp();
        }
    }

#pragma unroll
    for (int j = 0; j < 8; ++j) {
        const int l = qBase + ql0 + j;
        float inv = 1.0f / Sum[j];
        size_t ob = ((size_t)(b * Ntok + l)) * Dm + h * HD + 2 * lane;
        __nv_bfloat16 hx, lx, hy, ly;
        split_bf16(accX[j] * inv, hx, lx);
        split_bf16(accY[j] * inv, hy, ly);
        *(__nv_bfloat162*)(ohi + ob) = __nv_bfloat162(hx, hy);
        *(__nv_bfloat162*)(olo + ob) = __nv_bfloat162(lx, ly);
    }
}

// ---------------- final mean over tokens ----------------
__global__ void mean_kernel(const float* __restrict__ hln, float* __restrict__ enc) {
    int idx = blockIdx.x * blockDim.x + threadIdx.x;
    if (idx >= Bx * Dm) return;
    int b = idx / Dm, d = idx - b * Dm;
    float s = 0.f;
    const float* base = hln + (size_t)b * Ntok * Dm + d;
    for (int n = 0; n < Ntok; ++n) s += base[(size_t)n * Dm];
    enc[idx] = s * (1.0f / Ntok);
}

// ---------------- head ----------------
__global__ void head_kernel(const float* __restrict__ enc,
                            const float* __restrict__ h1w, const float* __restrict__ h1b,
                            const float* __restrict__ h2w, const float* __restrict__ h2b,
                            float* __restrict__ out) {
    __shared__ float es[Dm];
    __shared__ float ys[Dm / 2];
    int b = blockIdx.x, tid = threadIdx.x;
    for (int j = tid; j < Dm; j += blockDim.x) es[j] = enc[(size_t)b * Dm + j];
    __syncthreads();
    int j = tid;
    float s = h1b[j];
    const float* wr = h1w + (size_t)j * Dm;
#pragma unroll 4
    for (int d = 0; d < Dm; ++d) s = fmaf(es[d], wr[d], s);
    ys[j] = fmaxf(s, 0.f);
    __syncthreads();
    if (tid < 2) {
        float s2 = h2b[tid];
        const float* w2 = h2w + (size_t)tid * (Dm / 2);
        for (int q = 0; q < Dm / 2; ++q) s2 = fmaf(ys[q], w2[q], s2);
        out[b * 2 + tid] = s2;
    }
}

// ---------------- launch ----------------
extern "C" void kernel_launch(void* const* d_in, const int* in_sizes, int n_in,
                              void* d_out, int out_size) {
    const float* x     = (const float*)d_in[0];
    const float* pp_w  = (const float*)d_in[1];
    const float* pp_b  = (const float*)d_in[2];
    const float* pe    = (const float*)d_in[3];
    const float* ln1_g = (const float*)d_in[4];
    const float* ln1_b = (const float*)d_in[5];
    const float* qkv_w = (const float*)d_in[6];
    const float* out_w = (const float*)d_in[7];
    const float* ln2_g = (const float*)d_in[8];
    const float* ln2_b = (const float*)d_in[9];
    const float* fc1_w = (const float*)d_in[10];
    const float* fc2_w = (const float*)d_in[11];
    const float* lnf_g = (const float*)d_in[12];
    const float* lnf_b = (const float*)d_in[13];
    const float* h1_w  = (const float*)d_in[14];
    const float* h1_b  = (const float*)d_in[15];
    const float* h2_w  = (const float*)d_in[16];
    const float* h2_b  = (const float*)d_in[17];

    float *z, *h, *qkv, *enc;
    __nv_bfloat16 *hh, *hl, *oh, *ol, *fh, *fl;
    __nv_bfloat16 *wqh, *wql, *woh, *wol, *w1h, *w1l, *w2h, *w2l;
    cudaGetSymbolAddress((void**)&z,   g_z);
    cudaGetSymbolAddress((void**)&h,   g_h);
    cudaGetSymbolAddress((void**)&qkv, g_qkv);
    cudaGetSymbolAddress((void**)&enc, g_enc);
    cudaGetSymbolAddress((void**)&hh,  g_hh);  cudaGetSymbolAddress((void**)&hl, g_hl);
    cudaGetSymbolAddress((void**)&oh,  g_oh);  cudaGetSymbolAddress((void**)&ol, g_ol);
    cudaGetSymbolAddress((void**)&fh,  g_fh);  cudaGetSymbolAddress((void**)&fl, g_fl);
    cudaGetSymbolAddress((void**)&wqh, g_wqkv_h); cudaGetSymbolAddress((void**)&wql, g_wqkv_l);
    cudaGetSymbolAddress((void**)&woh, g_wout_h); cudaGetSymbolAddress((void**)&wol, g_wout_l);
    cudaGetSymbolAddress((void**)&w1h, g_wfc1_h); cudaGetSymbolAddress((void**)&w1l, g_wfc1_l);
    cudaGetSymbolAddress((void**)&w2h, g_wfc2_h); cudaGetSymbolAddress((void**)&w2l, g_wfc2_l);

    cudaFuncSetAttribute(wgemm<0>, cudaFuncAttributeMaxDynamicSharedMemorySize, GEMM_SMEM);
    cudaFuncSetAttribute(wgemm<1>, cudaFuncAttributeMaxDynamicSharedMemorySize, GEMM_SMEM);
    cudaFuncSetAttribute(wgemm<2>, cudaFuncAttributeMaxDynamicSharedMemorySize, GEMM_SMEM);
    cudaFuncSetAttribute(attn_kernel, cudaFuncAttributeMaxDynamicSharedMemorySize, ATT_SMEM);

    split_kernel<<<NQKV / 1024, 256>>>(qkv_w, wqh, wql, NQKV);
    split_kernel<<<NOUT / 1024, 256>>>(out_w, woh, wol, NOUT);
    split_kernel<<<NFC1 / 1024, 256>>>(fc1_w, w1h, w1l, NFC1);
    split_kernel<<<NFC2 / 1024, 256>>>(fc2_w, w2h, w2l, NFC2);

    patch_embed_kernel<<<(Mrows * Dm + 255) / 256, 256>>>(x, pp_w, pp_b, pe, z);

    for (int i = 0; i < NL; ++i) {
        ln_kernel<1><<<Mrows / 8, 256>>>(z, ln1_g + i * Dm, ln1_b + i * Dm, nullptr, hh, hl);
        wgemm<0><<<dim3((3 * Dm) / 128, Mrows / 128), 256, GEMM_SMEM>>>(
            hh, hl, wqh + (size_t)i * 3 * Dm * Dm, wql + (size_t)i * 3 * Dm * Dm,
            nullptr, qkv, nullptr, nullptr, 3 * Dm, Dm);
        attn_kernel<<<dim3(Ntok / 64, Hh, Bx), 256, ATT_SMEM>>>(qkv, oh, ol);
        wgemm<1><<<dim3(Dm / 128, Mrows / 128), 256, GEMM_SMEM>>>(
            oh, ol, woh + (size_t)i * Dm * Dm, wol + (size_t)i * Dm * Dm,
            z, z, nullptr, nullptr, Dm, Dm);
        ln_kernel<1><<<Mrows / 8, 256>>>(z, ln2_g + i * Dm, ln2_b + i * Dm, nullptr, hh, hl);
        wgemm<2><<<dim3(DFF / 128, Mrows / 128), 256, GEMM_SMEM>>>(
            hh, hl, w1h + (size_t)i * DFF * Dm, w1l + (size_t)i * DFF * Dm,
            nullptr, nullptr, fh, fl, DFF, Dm);
        wgemm<1><<<dim3(Dm / 128, Mrows / 128), 256, GEMM_SMEM>>>(
            fh, fl, w2h + (size_t)i * Dm * DFF, w2l + (size_t)i * Dm * DFF,
            z, z, nullptr, nullptr, Dm, DFF);
    }

    ln_kernel<0><<<Mrows / 8, 256>>>(z, lnf_g, lnf_b, h, nullptr, nullptr);
    mean_kernel<<<(Bx * Dm + 255) / 256, 256>>>(h, enc);
    head_kernel<<<Bx, Dm / 2>>>(enc, h1_w, h1_b, h2_w, h2_b, (float*)d_out);
}

// round 15
// speedup vs baseline: 1.1600x; 1.1600x over previous
#include <cuda_runtime.h>
#include <cuda_bf16.h>
#include <cstdint>
#include <math.h>

#define Bx 8
#define Ntok 512
#define Dm 768
#define Hh 12
#define HD 64
#define NL 6
#define DFF 3072
#define Mrows (Bx * Ntok)      // 4096
#define Tlen 8192
#define PATCH 16

// ---------------- scratch (device globals; no allocation) ----------------
__device__ float g_z[Mrows * Dm];
__device__ float g_h[Mrows * Dm];
__device__ float g_enc[Bx * Dm];

__device__ __nv_bfloat16 g_qkvh[Mrows * 3 * Dm], g_qkvl[Mrows * 3 * Dm];
__device__ __nv_bfloat16 g_hh[Mrows * Dm],  g_hl[Mrows * Dm];
__device__ __nv_bfloat16 g_oh[Mrows * Dm],  g_ol[Mrows * Dm];
__device__ __nv_bfloat16 g_fh[Mrows * DFF], g_fl[Mrows * DFF];

#define NQKV (NL * 3 * Dm * Dm)
#define NOUT (NL * Dm * Dm)
#define NFC1 (NL * DFF * Dm)
#define NFC2 (NL * Dm * DFF)
__device__ __nv_bfloat16 g_wqkv_h[NQKV], g_wqkv_l[NQKV];
__device__ __nv_bfloat16 g_wout_h[NOUT], g_wout_l[NOUT];
__device__ __nv_bfloat16 g_wfc1_h[NFC1], g_wfc1_l[NFC1];
__device__ __nv_bfloat16 g_wfc2_h[NFC2], g_wfc2_l[NFC2];

// ---------------- helpers ----------------
__device__ __forceinline__ void split_bf16(float x, __nv_bfloat16& h, __nv_bfloat16& l) {
    h = __float2bfloat16_rn(x);
    l = __float2bfloat16_rn(x - __bfloat162float(h));
}
__device__ __forceinline__ uint32_t sw128(uint32_t o) { return o ^ ((o >> 3) & 0x70); }
__device__ __forceinline__ uint32_t smem_u32(const void* p) {
    return (uint32_t)__cvta_generic_to_shared(p);
}
__device__ __forceinline__ void cp16(uint32_t dst, const void* src) {
    asm volatile("cp.async.cg.shared.global [%0], [%1], 16;" :: "r"(dst), "l"(src));
}
__device__ __forceinline__ void ldmx4(uint32_t* r, uint32_t addr) {
    asm volatile("ldmatrix.sync.aligned.m8n8.x4.shared.b16 {%0,%1,%2,%3}, [%4];"
                 : "=r"(r[0]), "=r"(r[1]), "=r"(r[2]), "=r"(r[3]) : "r"(addr));
}
__device__ __forceinline__ void ldmx4t(uint32_t* r, uint32_t addr) {
    asm volatile("ldmatrix.sync.aligned.m8n8.x4.trans.shared.b16 {%0,%1,%2,%3}, [%4];"
                 : "=r"(r[0]), "=r"(r[1]), "=r"(r[2]), "=r"(r[3]) : "r"(addr));
}
__device__ __forceinline__ void mma16(float* c, const uint32_t* a, const uint32_t* b) {
    asm volatile("mma.sync.aligned.m16n8k16.row.col.f32.bf16.bf16.f32 "
                 "{%0,%1,%2,%3}, {%4,%5,%6,%7}, {%8,%9}, {%0,%1,%2,%3};"
                 : "+f"(c[0]), "+f"(c[1]), "+f"(c[2]), "+f"(c[3])
                 : "r"(a[0]), "r"(a[1]), "r"(a[2]), "r"(a[3]),
                   "r"(b[0]), "r"(b[1]));
}

// ---------------- weight split (vectorized x4) ----------------
__global__ void split_kernel(const float* __restrict__ src,
                             __nv_bfloat16* __restrict__ hi,
                             __nv_bfloat16* __restrict__ lo, int n) {
    int i = (blockIdx.x * 256 + threadIdx.x) * 4;
    if (i >= n) return;
    float4 v = *(const float4*)(src + i);
    __nv_bfloat16 h0, l0, h1, l1, h2, l2, h3, l3;
    split_bf16(v.x, h0, l0); split_bf16(v.y, h1, l1);
    split_bf16(v.z, h2, l2); split_bf16(v.w, h3, l3);
    ushort4 hv, lv;
    hv.x = *(uint16_t*)&h0; hv.y = *(uint16_t*)&h1; hv.z = *(uint16_t*)&h2; hv.w = *(uint16_t*)&h3;
    lv.x = *(uint16_t*)&l0; lv.y = *(uint16_t*)&l1; lv.z = *(uint16_t*)&l2; lv.w = *(uint16_t*)&l3;
    *(ushort4*)(hi + i) = hv;
    *(ushort4*)(lo + i) = lv;
}

// ---------------- patch embed + positional ----------------
__global__ void patch_embed_kernel(const float* __restrict__ x,
                                   const float* __restrict__ pp_w,
                                   const float* __restrict__ pp_b,
                                   const float* __restrict__ pe,
                                   float* __restrict__ z) {
    int idx = blockIdx.x * blockDim.x + threadIdx.x;
    if (idx >= Mrows * Dm) return;
    int row = idx / Dm;
    int d   = idx - row * Dm;
    int b = row >> 9;
    int n = row & 511;
    const float* xr = x + (size_t)b * Tlen + n * PATCH;
    const float* wr = pp_w + (size_t)d * PATCH;
    float s = pp_b[d];
#pragma unroll
    for (int p = 0; p < PATCH; ++p) s += xr[p] * wr[p];
    z[idx] = s + pe[(size_t)n * Dm + d];
}

// ---------------- LayerNorm: warp per row ----------------
template<int OUT>
__global__ __launch_bounds__(256)
void ln_kernel(const float* __restrict__ X,
               const float* __restrict__ gam,
               const float* __restrict__ bet,
               float* __restrict__ Yf,
               __nv_bfloat16* __restrict__ Yh,
               __nv_bfloat16* __restrict__ Yl) {
    const int warp = threadIdx.x >> 5, lane = threadIdx.x & 31;
    const int row = blockIdx.x * 8 + warp;
    const float4* xr = (const float4*)(X + (size_t)row * Dm);
    float4 v[6];
    float s = 0.f;
#pragma unroll
    for (int k = 0; k < 6; ++k) {
        v[k] = xr[lane + 32 * k];
        s += v[k].x + v[k].y + v[k].z + v[k].w;
    }
#pragma unroll
    for (int off = 16; off > 0; off >>= 1) s += __shfl_xor_sync(0xFFFFFFFFu, s, off);
    const float mean = s * (1.0f / Dm);
    float var = 0.f;
#pragma unroll
    for (int k = 0; k < 6; ++k) {
        float a = v[k].x - mean, b = v[k].y - mean, c = v[k].z - mean, d = v[k].w - mean;
        var += a * a + b * b + c * c + d * d;
    }
#pragma unroll
    for (int off = 16; off > 0; off >>= 1) var += __shfl_xor_sync(0xFFFFFFFFu, var, off);
    const float rstd = rsqrtf(var * (1.0f / Dm) + 1e-5f);

#pragma unroll
    for (int k = 0; k < 6; ++k) {
        int j4 = lane + 32 * k;
        float4 g = ((const float4*)gam)[j4];
        float4 b = ((const float4*)bet)[j4];
        float y0 = (v[k].x - mean) * rstd * g.x + b.x;
        float y1 = (v[k].y - mean) * rstd * g.y + b.y;
        float y2 = (v[k].z - mean) * rstd * g.z + b.z;
        float y3 = (v[k].w - mean) * rstd * g.w + b.w;
        if (OUT == 0) {
            ((float4*)(Yf + (size_t)row * Dm))[j4] = make_float4(y0, y1, y2, y3);
        } else {
            __nv_bfloat16 h0, l0, h1, l1, h2, l2, h3, l3;
            split_bf16(y0, h0, l0); split_bf16(y1, h1, l1);
            split_bf16(y2, h2, l2); split_bf16(y3, h3, l3);
            ushort4 hv, lv;
            hv.x = *(uint16_t*)&h0; hv.y = *(uint16_t*)&h1;
            hv.z = *(uint16_t*)&h2; hv.w = *(uint16_t*)&h3;
            lv.x = *(uint16_t*)&l0; lv.y = *(uint16_t*)&l1;
            lv.z = *(uint16_t*)&l2; lv.w = *(uint16_t*)&l3;
            ((ushort4*)(Yh + (size_t)row * Dm))[j4] = hv;
            ((ushort4*)(Yl + (size_t)row * Dm))[j4] = lv;
        }
    }
}

// ---------------- bf16x3 mma.sync GEMM, KTILE=64, 3 stages ----------------
// EPI: 0 fp32; 1 fp32 Res+AB; 2 gelu->(hi,lo); 3 plain ->(hi,lo)
#define KTILE 64
#define ST_OP 16384
#define STG (4 * ST_OP)
#define NSTAGE 3
#define GEMM_SMEM (NSTAGE * STG + 1024)

template<int EPI>
__global__ __launch_bounds__(256, 1)
void wgemm(const __nv_bfloat16* __restrict__ Ah, const __nv_bfloat16* __restrict__ Al,
           const __nv_bfloat16* __restrict__ Wh, const __nv_bfloat16* __restrict__ Wl,
           const float* __restrict__ Res, float* __restrict__ Cf,
           __nv_bfloat16* __restrict__ Chi, __nv_bfloat16* __restrict__ Clo,
           int Nn, int K) {
    extern __shared__ char dyn_smem[];
    const int tid = threadIdx.x, lane = tid & 31, wid = tid >> 5;
    const int warpM = wid & 1, warpN = wid >> 1;
    uint32_t raw = smem_u32(dyn_smem);
    uint32_t sb0 = (raw + 1023u) & ~1023u;

    const int mBase = blockIdx.y * 128, nBase = blockIdx.x * 128;
    const int KT = K >> 6;

    uint32_t swl[4];
    const __nv_bfloat16 *pAh[4], *pAl[4], *pWh[4], *pWl[4];
#pragma unroll
    for (int i = 0; i < 4; ++i) {
        int q = tid + i * 256;
        int row = q >> 3, c = q & 7;
        swl[i] = sw128((uint32_t)(row * 128 + c * 16));
        size_t ga = (size_t)(mBase + row) * K + c * 8;
        size_t gw = (size_t)(nBase + row) * K + c * 8;
        pAh[i] = Ah + ga; pAl[i] = Al + ga;
        pWh[i] = Wh + gw; pWl[i] = Wl + gw;
    }

    float acc[4][4][4];
#pragma unroll
    for (int i = 0; i < 4; ++i)
#pragma unroll
        for (int j = 0; j < 4; ++j)
#pragma unroll
            for (int q = 0; q < 4; ++q) acc[i][j][q] = 0.f;

#define LOADSTG(kt)                                                              \
    do {                                                                         \
        const int kofs_ = (kt) * KTILE;                                          \
        const uint32_t sb_ = sb0 + ((kt) % NSTAGE) * STG;                        \
        _Pragma("unroll")                                                        \
        for (int i_ = 0; i_ < 4; ++i_) {                                         \
            cp16(sb_ + swl[i_],              pAh[i_] + kofs_);                   \
            cp16(sb_ + ST_OP + swl[i_],      pAl[i_] + kofs_);                   \
            cp16(sb_ + 2 * ST_OP + swl[i_],  pWh[i_] + kofs_);                   \
            cp16(sb_ + 3 * ST_OP + swl[i_],  pWl[i_] + kofs_);                   \
        }                                                                        \
        asm volatile("cp.async.commit_group;" ::: "memory");                     \
    } while (0)

    LOADSTG(0);
    LOADSTG(1);

    const int arow = warpM * 64 + (lane & 15);
    const int akb  = (lane >> 4) << 4;
    const int bprow = warpN * 32 + ((lane >> 4) & 1) * 8 + (lane & 7);
    const int bpkb  = ((lane >> 3) & 1) << 4;

    for (int kt = 0; kt < KT; ++kt) {
        if (kt + 1 < KT) {
            asm volatile("cp.async.wait_group 1;" ::: "memory");
        } else {
            asm volatile("cp.async.wait_group 0;" ::: "memory");
        }
        __syncthreads();
        if (kt + 2 < KT) LOADSTG(kt + 2);

        const uint32_t A0 = sb0 + (kt % NSTAGE) * STG;
        const uint32_t W0 = A0 + 2 * ST_OP;

#pragma unroll
        for (int kc = 0; kc < 4; ++kc) {
            uint32_t ah[4][4], al[4][4];
#pragma unroll
            for (int i = 0; i < 4; ++i) {
                uint32_t off = sw128((uint32_t)((arow + i * 16) * 128 + kc * 32 + akb));
                ldmx4(ah[i], A0 + off);
                ldmx4(al[i], A0 + ST_OP + off);
            }
            uint32_t bh[4][2], bl[4][2];
#pragma unroll
            for (int jp = 0; jp < 2; ++jp) {
                uint32_t off = sw128((uint32_t)((bprow + jp * 16) * 128 + kc * 32 + bpkb));
                uint32_t r[4];
                ldmx4(r, W0 + off);
                bh[2 * jp][0] = r[0]; bh[2 * jp][1] = r[1];
                bh[2 * jp + 1][0] = r[2]; bh[2 * jp + 1][1] = r[3];
                ldmx4(r, W0 + ST_OP + off);
                bl[2 * jp][0] = r[0]; bl[2 * jp][1] = r[1];
                bl[2 * jp + 1][0] = r[2]; bl[2 * jp + 1][1] = r[3];
            }
#pragma unroll
            for (int i = 0; i < 4; ++i)
#pragma unroll
                for (int j = 0; j < 4; ++j) {
                    mma16(acc[i][j], ah[i], bh[j]);
                    mma16(acc[i][j], ah[i], bl[j]);
                    mma16(acc[i][j], al[i], bh[j]);
                }
        }
    }

    const int erow = warpM * 64 + (lane >> 2);
    const int ecol = warpN * 32 + (lane & 3) * 2;
#pragma unroll
    for (int i = 0; i < 4; ++i) {
        int row0 = mBase + erow + i * 16;
#pragma unroll
        for (int j = 0; j < 4; ++j) {
            int col = nBase + ecol + j * 8;
            size_t g0 = (size_t)row0 * Nn + col;
            size_t g1 = g0 + (size_t)8 * Nn;
            float v0 = acc[i][j][0], v1 = acc[i][j][1];
            float v2 = acc[i][j][2], v3 = acc[i][j][3];
            if (EPI == 0) {
                *(float2*)(Cf + g0) = make_float2(v0, v1);
                *(float2*)(Cf + g1) = make_float2(v2, v3);
            } else if (EPI == 1) {
                float2 r0 = *(const float2*)(Res + g0);
                float2 r1 = *(const float2*)(Res + g1);
                *(float2*)(Cf + g0) = make_float2(v0 + r0.x, v1 + r0.y);
                *(float2*)(Cf + g1) = make_float2(v2 + r1.x, v3 + r1.y);
            } else {
                if (EPI == 2) {
                    v0 = 0.5f * v0 * (1.0f + erff(v0 * 0.70710678118654752f));
                    v1 = 0.5f * v1 * (1.0f + erff(v1 * 0.70710678118654752f));
                    v2 = 0.5f * v2 * (1.0f + erff(v2 * 0.70710678118654752f));
                    v3 = 0.5f * v3 * (1.0f + erff(v3 * 0.70710678118654752f));
                }
                __nv_bfloat16 h0, l0, h1, l1, h2, l2, h3, l3;
                split_bf16(v0, h0, l0); split_bf16(v1, h1, l1);
                split_bf16(v2, h2, l2); split_bf16(v3, h3, l3);
                *(__nv_bfloat162*)(Chi + g0) = __nv_bfloat162(h0, h1);
                *(__nv_bfloat162*)(Clo + g0) = __nv_bfloat162(l0, l1);
                *(__nv_bfloat162*)(Chi + g1) = __nv_bfloat162(h2, h3);
                *(__nv_bfloat162*)(Clo + g1) = __nv_bfloat162(l2, l3);
            }
        }
    }
}

// ---------------- causal attention v6: warp-mma (FA2-style), bf16x3 ----------------
// CTA = (b, h, 64 queries), 4 warps x 16 query rows. smem: QH QL KH KL VH VL (8KB each)
#define A_QH 0
#define A_QL 8192
#define A_KH 16384
#define A_KL 24576
#define A_VH 32768
#define A_VL 40960
#define ATT_SMEM 49152

__global__ __launch_bounds__(128)
void attn_kernel(const __nv_bfloat16* __restrict__ qkvh,
                 const __nv_bfloat16* __restrict__ qkvl,
                 __nv_bfloat16* __restrict__ ohi, __nv_bfloat16* __restrict__ olo) {
    extern __shared__ char asm_[];
    const uint32_t sb = smem_u32(asm_);
    const int b = blockIdx.z, h = blockIdx.y;
    const int qb = gridDim.x - 1 - blockIdx.x;   // heavy first
    const int tid = threadIdx.x, lane = tid & 31, w = tid >> 5;
    const int qBase = qb * 64;

    {
#pragma unroll
        for (int i = 0; i < 4; ++i) {
            int q = tid + i * 128;
            int row = q >> 3, c = q & 7;
            uint32_t sw = sw128((uint32_t)(row * 128 + c * 16));
            size_t gq = (size_t)(b * Ntok + qBase + row) * (3 * Dm) + h * HD + c * 8;
            cp16(sb + A_QH + sw, qkvh + gq);
            cp16(sb + A_QL + sw, qkvl + gq);
            size_t gk = (size_t)(b * Ntok + row) * (3 * Dm) + Dm + h * HD + c * 8;
            cp16(sb + A_KH + sw, qkvh + gk);
            cp16(sb + A_KL + sw, qkvl + gk);
            cp16(sb + A_VH + sw, qkvh + gk + Dm);
            cp16(sb + A_VL + sw, qkvl + gk + Dm);
        }
        asm volatile("cp.async.commit_group;" ::: "memory");
        asm volatile("cp.async.wait_group 0;" ::: "memory");
        __syncthreads();
    }

    uint32_t qh[4][4], ql[4][4];
    {
        const int arow = w * 16 + (lane & 15);
        const int akb  = (lane >> 4) << 4;
#pragma unroll
        for (int kc = 0; kc < 4; ++kc) {
            uint32_t off = sw128((uint32_t)(arow * 128 + kc * 32 + akb));
            ldmx4(qh[kc], sb + A_QH + off);
            ldmx4(ql[kc], sb + A_QL + off);
        }
    }

    float oacc[8][4];
#pragma unroll
    for (int n = 0; n < 8; ++n)
#pragma unroll
        for (int q = 0; q < 4; ++q) oacc[n][q] = 0.f;
    float M0 = -INFINITY, M1 = -INFINITY, Sum0 = 0.f, Sum1 = 0.f;

    const int row0 = qBase + w * 16 + (lane >> 2);
    const int row1 = row0 + 8;
    const int colq = (lane & 3) * 2;

    const int bprow = ((lane >> 4) & 1) * 8 + (lane & 7);
    const int bpkb  = ((lane >> 3) & 1) << 4;
    const int vrow = lane & 15;
    const int vcb  = (lane & 16) ? 16 : 0;

    for (int c = 0; c <= qb; ++c) {
        if (c > 0) {
            __syncthreads();
#pragma unroll
            for (int i = 0; i < 4; ++i) {
                int q = tid + i * 128;
                int row = q >> 3, cc = q & 7;
                uint32_t sw = sw128((uint32_t)(row * 128 + cc * 16));
                size_t gk = (size_t)(b * Ntok + c * 64 + row) * (3 * Dm) + Dm + h * HD + cc * 8;
                cp16(sb + A_KH + sw, qkvh + gk);
                cp16(sb + A_KL + sw, qkvl + gk);
                cp16(sb + A_VH + sw, qkvh + gk + Dm);
                cp16(sb + A_VL + sw, qkvl + gk + Dm);
            }
            asm volatile("cp.async.commit_group;" ::: "memory");
            asm volatile("cp.async.wait_group 0;" ::: "memory");
            __syncthreads();
        }

        float sacc[8][4];
#pragma unroll
        for (int n = 0; n < 8; ++n)
#pragma unroll
            for (int q = 0; q < 4; ++q) sacc[n][q] = 0.f;

#pragma unroll
        for (int kc = 0; kc < 4; ++kc) {
            uint32_t kh[8][2], kl[8][2];
#pragma unroll
            for (int p = 0; p < 4; ++p) {
                uint32_t off = sw128((uint32_t)((p * 16 + bprow) * 128 + kc * 32 + bpkb));
                uint32_t r[4];
                ldmx4(r, sb + A_KH + off);
                kh[2 * p][0] = r[0]; kh[2 * p][1] = r[1];
                kh[2 * p + 1][0] = r[2]; kh[2 * p + 1][1] = r[3];
                ldmx4(r, sb + A_KL + off);
                kl[2 * p][0] = r[0]; kl[2 * p][1] = r[1];
                kl[2 * p + 1][0] = r[2]; kl[2 * p + 1][1] = r[3];
            }
#pragma unroll
            for (int n = 0; n < 8; ++n) {
                mma16(sacc[n], qh[kc], kh[n]);
                mma16(sacc[n], qh[kc], kl[n]);
                mma16(sacc[n], ql[kc], kh[n]);
            }
        }

        const int kb = c * 64 + colq;
#pragma unroll
        for (int n = 0; n < 8; ++n) {
            int k0 = kb + n * 8, k1 = k0 + 1;
            sacc[n][0] = (k0 > row0) ? -INFINITY : sacc[n][0] * 0.125f;
            sacc[n][1] = (k1 > row0) ? -INFINITY : sacc[n][1] * 0.125f;
            sacc[n][2] = (k0 > row1) ? -INFINITY : sacc[n][2] * 0.125f;
            sacc[n][3] = (k1 > row1) ? -INFINITY : sacc[n][3] * 0.125f;
        }

        float rm0 = -INFINITY, rm1 = -INFINITY;
#pragma unroll
        for (int n = 0; n < 8; ++n) {
            rm0 = fmaxf(rm0, fmaxf(sacc[n][0], sacc[n][1]));
            rm1 = fmaxf(rm1, fmaxf(sacc[n][2], sacc[n][3]));
        }
        rm0 = fmaxf(rm0, __shfl_xor_sync(0xFFFFFFFFu, rm0, 1));
        rm0 = fmaxf(rm0, __shfl_xor_sync(0xFFFFFFFFu, rm0, 2));
        rm1 = fmaxf(rm1, __shfl_xor_sync(0xFFFFFFFFu, rm1, 1));
        rm1 = fmaxf(rm1, __shfl_xor_sync(0xFFFFFFFFu, rm1, 2));
        float nM0 = fmaxf(M0, rm0), nM1 = fmaxf(M1, rm1);
        float sc0 = __expf(M0 - nM0), sc1 = __expf(M1 - nM1);
        float rs0 = 0.f, rs1 = 0.f;
#pragma unroll
        for (int n = 0; n < 8; ++n) {
            float p0 = (sacc[n][0] == -INFINITY) ? 0.f : __expf(sacc[n][0] - nM0);
            float p1 = (sacc[n][1] == -INFINITY) ? 0.f : __expf(sacc[n][1] - nM0);
            float p2 = (sacc[n][2] == -INFINITY) ? 0.f : __expf(sacc[n][2] - nM1);
            float p3 = (sacc[n][3] == -INFINITY) ? 0.f : __expf(sacc[n][3] - nM1);
            sacc[n][0] = p0; sacc[n][1] = p1; sacc[n][2] = p2; sacc[n][3] = p3;
            rs0 += p0 + p1; rs1 += p2 + p3;
        }
        rs0 += __shfl_xor_sync(0xFFFFFFFFu, rs0, 1);
        rs0 += __shfl_xor_sync(0xFFFFFFFFu, rs0, 2);
        rs1 += __shfl_xor_sync(0xFFFFFFFFu, rs1, 1);
        rs1 += __shfl_xor_sync(0xFFFFFFFFu, rs1, 2);
        Sum0 = Sum0 * sc0 + rs0; Sum1 = Sum1 * sc1 + rs1;
        M0 = nM0; M1 = nM1;
#pragma unroll
        for (int n = 0; n < 8; ++n) {
            oacc[n][0] *= sc0; oacc[n][1] *= sc0;
            oacc[n][2] *= sc1; oacc[n][3] *= sc1;
        }

        uint32_t ph[4][4], pl[4][4];
#pragma unroll
        for (int s = 0; s < 4; ++s) {
#pragma unroll
            for (int half = 0; half < 2; ++half) {
                int t = 2 * s + half;
                float v0 = sacc[t][0], v1 = sacc[t][1], v2 = sacc[t][2], v3 = sacc[t][3];
                __nv_bfloat16 h0, l0, h1, l1, h2, l2, h3, l3;
                split_bf16(v0, h0, l0); split_bf16(v1, h1, l1);
                split_bf16(v2, h2, l2); split_bf16(v3, h3, l3);
                __nv_bfloat162 ph01(h0, h1), ph23(h2, h3), pl01(l0, l1), pl23(l2, l3);
                ph[s][2 * half + 0] = *(uint32_t*)&ph01;
                ph[s][2 * half + 1] = *(uint32_t*)&ph23;
                pl[s][2 * half + 0] = *(uint32_t*)&pl01;
                pl[s][2 * half + 1] = *(uint32_t*)&pl23;
            }
        }

#pragma unroll
        for (int s = 0; s < 4; ++s) {
            uint32_t vh[8][2], vl[8][2];
#pragma unroll
            for (int p = 0; p < 4; ++p) {
                uint32_t off = sw128((uint32_t)((s * 16 + vrow) * 128 + p * 32 + vcb));
                uint32_t r[4];
                ldmx4t(r, sb + A_VH + off);
                vh[2 * p][0] = r[0]; vh[2 * p][1] = r[1];
                vh[2 * p + 1][0] = r[2]; vh[2 * p + 1][1] = r[3];
                ldmx4t(r, sb + A_VL + off);
                vl[2 * p][0] = r[0]; vl[2 * p][1] = r[1];
                vl[2 * p + 1][0] = r[2]; vl[2 * p + 1][1] = r[3];
            }
#pragma unroll
            for (int n = 0; n < 8; ++n) {
                mma16(oacc[n], ph[s], vh[n]);
                mma16(oacc[n], ph[s], vl[n]);
                mma16(oacc[n], pl[s], vh[n]);
            }
        }
    }

    const float inv0 = 1.0f / Sum0, inv1 = 1.0f / Sum1;
    const size_t tok0 = (size_t)(b * Ntok + row0) * Dm + h * HD;
    const size_t tok1 = (size_t)(b * Ntok + row1) * Dm + h * HD;
#pragma unroll
    for (int n = 0; n < 8; ++n) {
        int d = n * 8 + colq;
        float v0 = oacc[n][0] * inv0, v1 = oacc[n][1] * inv0;
        float v2 = oacc[n][2] * inv1, v3 = oacc[n][3] * inv1;
        __nv_bfloat16 h0, l0, h1, l1, h2, l2, h3, l3;
        split_bf16(v0, h0, l0); split_bf16(v1, h1, l1);
        split_bf16(v2, h2, l2); split_bf16(v3, h3, l3);
        *(__nv_bfloat162*)(ohi + tok0 + d) = __nv_bfloat162(h0, h1);
        *(__nv_bfloat162*)(olo + tok0 + d) = __nv_bfloat162(l0, l1);
        *(__nv_bfloat162*)(ohi + tok1 + d) = __nv_bfloat162(h2, h3);
        *(__nv_bfloat162*)(olo + tok1 + d) = __nv_bfloat162(l2, l3);
    }
}

// ---------------- final mean over tokens ----------------
__global__ void mean_kernel(const float* __restrict__ hln, float* __restrict__ enc) {
    int idx = blockIdx.x * blockDim.x + threadIdx.x;
    if (idx >= Bx * Dm) return;
    int b = idx / Dm, d = idx - b * Dm;
    float s = 0.f;
    const float* base = hln + (size_t)b * Ntok * Dm + d;
    for (int n = 0; n < Ntok; ++n) s += base[(size_t)n * Dm];
    enc[idx] = s * (1.0f / Ntok);
}

// ---------------- head ----------------
__global__ void head_kernel(const float* __restrict__ enc,
                            const float* __restrict__ h1w, const float* __restrict__ h1b,
                            const float* __restrict__ h2w, const float* __restrict__ h2b,
                            float* __restrict__ out) {
    __shared__ float es[Dm];
    __shared__ float ys[Dm / 2];
    int b = blockIdx.x, tid = threadIdx.x;
    for (int j = tid; j < Dm; j += blockDim.x) es[j] = enc[(size_t)b * Dm + j];
    __syncthreads();
    int j = tid;
    float s = h1b[j];
    const float* wr = h1w + (size_t)j * Dm;
#pragma unroll 4
    for (int d = 0; d < Dm; ++d) s = fmaf(es[d], wr[d], s);
    ys[j] = fmaxf(s, 0.f);
    __syncthreads();
    if (tid < 2) {
        float s2 = h2b[tid];
        const float* w2 = h2w + (size_t)tid * (Dm / 2);
        for (int q = 0; q < Dm / 2; ++q) s2 = fmaf(ys[q], w2[q], s2);
        out[b * 2 + tid] = s2;
    }
}

// ---------------- launch ----------------
extern "C" void kernel_launch(void* const* d_in, const int* in_sizes, int n_in,
                              void* d_out, int out_size) {
    const float* x     = (const float*)d_in[0];
    const float* pp_w  = (const float*)d_in[1];
    const float* pp_b  = (const float*)d_in[2];
    const float* pe    = (const float*)d_in[3];
    const float* ln1_g = (const float*)d_in[4];
    const float* ln1_b = (const float*)d_in[5];
    const float* qkv_w = (const float*)d_in[6];
    const float* out_w = (const float*)d_in[7];
    const float* ln2_g = (const float*)d_in[8];
    const float* ln2_b = (const float*)d_in[9];
    const float* fc1_w = (const float*)d_in[10];
    const float* fc2_w = (const float*)d_in[11];
    const float* lnf_g = (const float*)d_in[12];
    const float* lnf_b = (const float*)d_in[13];
    const float* h1_w  = (const float*)d_in[14];
    const float* h1_b  = (const float*)d_in[15];
    const float* h2_w  = (const float*)d_in[16];
    const float* h2_b  = (const float*)d_in[17];

    float *z, *h, *enc;
    __nv_bfloat16 *qvh, *qvl, *hh, *hl, *oh, *ol, *fh, *fl;
    __nv_bfloat16 *wqh, *wql, *woh, *wol, *w1h, *w1l, *w2h, *w2l;
    cudaGetSymbolAddress((void**)&z,   g_z);
    cudaGetSymbolAddress((void**)&h,   g_h);
    cudaGetSymbolAddress((void**)&enc, g_enc);
    cudaGetSymbolAddress((void**)&qvh, g_qkvh); cudaGetSymbolAddress((void**)&qvl, g_qkvl);
    cudaGetSymbolAddress((void**)&hh,  g_hh);  cudaGetSymbolAddress((void**)&hl, g_hl);
    cudaGetSymbolAddress((void**)&oh,  g_oh);  cudaGetSymbolAddress((void**)&ol, g_ol);
    cudaGetSymbolAddress((void**)&fh,  g_fh);  cudaGetSymbolAddress((void**)&fl, g_fl);
    cudaGetSymbolAddress((void**)&wqh, g_wqkv_h); cudaGetSymbolAddress((void**)&wql, g_wqkv_l);
    cudaGetSymbolAddress((void**)&woh, g_wout_h); cudaGetSymbolAddress((void**)&wol, g_wout_l);
    cudaGetSymbolAddress((void**)&w1h, g_wfc1_h); cudaGetSymbolAddress((void**)&w1l, g_wfc1_l);
    cudaGetSymbolAddress((void**)&w2h, g_wfc2_h); cudaGetSymbolAddress((void**)&w2l, g_wfc2_l);

    cudaFuncSetAttribute(wgemm<0>, cudaFuncAttributeMaxDynamicSharedMemorySize, GEMM_SMEM);
    cudaFuncSetAttribute(wgemm<1>, cudaFuncAttributeMaxDynamicSharedMemorySize, GEMM_SMEM);
    cudaFuncSetAttribute(wgemm<2>, cudaFuncAttributeMaxDynamicSharedMemorySize, GEMM_SMEM);
    cudaFuncSetAttribute(wgemm<3>, cudaFuncAttributeMaxDynamicSharedMemorySize, GEMM_SMEM);
    cudaFuncSetAttribute(attn_kernel, cudaFuncAttributeMaxDynamicSharedMemorySize, ATT_SMEM);

    split_kernel<<<NQKV / 1024, 256>>>(qkv_w, wqh, wql, NQKV);
    split_kernel<<<NOUT / 1024, 256>>>(out_w, woh, wol, NOUT);
    split_kernel<<<NFC1 / 1024, 256>>>(fc1_w, w1h, w1l, NFC1);
    split_kernel<<<NFC2 / 1024, 256>>>(fc2_w, w2h, w2l, NFC2);

    patch_embed_kernel<<<(Mrows * Dm + 255) / 256, 256>>>(x, pp_w, pp_b, pe, z);

    for (int i = 0; i < NL; ++i) {
        ln_kernel<1><<<Mrows / 8, 256>>>(z, ln1_g + i * Dm, ln1_b + i * Dm, nullptr, hh, hl);
        wgemm<3><<<dim3((3 * Dm) / 128, Mrows / 128), 256, GEMM_SMEM>>>(
            hh, hl, wqh + (size_t)i * 3 * Dm * Dm, wql + (size_t)i * 3 * Dm * Dm,
            nullptr, nullptr, qvh, qvl, 3 * Dm, Dm);
        attn_kernel<<<dim3(Ntok / 64, Hh, Bx), 128, ATT_SMEM>>>(qvh, qvl, oh, ol);
        wgemm<1><<<dim3(Dm / 128, Mrows / 128), 256, GEMM_SMEM>>>(
            oh, ol, woh + (size_t)i * Dm * Dm, wol + (size_t)i * Dm * Dm,
            z, z, nullptr, nullptr, Dm, Dm);
        ln_kernel<1><<<Mrows / 8, 256>>>(z, ln2_g + i * Dm, ln2_b + i * Dm, nullptr, hh, hl);
        wgemm<2><<<dim3(DFF / 128, Mrows / 128), 256, GEMM_SMEM>>>(
            hh, hl, w1h + (size_t)i * DFF * Dm, w1l + (size_t)i * DFF * Dm,
            nullptr, nullptr, fh, fl, DFF, Dm);
        wgemm<1><<<dim3(Dm / 128, Mrows / 128), 256, GEMM_SMEM>>>(
            fh, fl, w2h + (size_t)i * Dm * DFF, w2l + (size_t)i * Dm * DFF,
            z, z, nullptr, nullptr, Dm, DFF);
    }

    ln_kernel<0><<<Mrows / 8, 256>>>(z, lnf_g, lnf_b, h, nullptr, nullptr);
    mean_kernel<<<(Bx * Dm + 255) / 256, 256>>>(h, enc);
    head_kernel<<<Bx, Dm / 2>>>(enc, h1_w, h1_b, h2_w, h2_b, (float*)d_out);
}

// round 16
// speedup vs baseline: 1.1630x; 1.0025x over previous
#include <cuda_runtime.h>
#include <cuda_bf16.h>
#include <cstdint>
#include <math.h>

#define Bx 8
#define Ntok 512
#define Dm 768
#define Hh 12
#define HD 64
#define NL 6
#define DFF 3072
#define Mrows (Bx * Ntok)      // 4096
#define Tlen 8192
#define PATCH 16

// ---------------- scratch (device globals; no allocation) ----------------
__device__ float g_z[Mrows * Dm];
__device__ float g_h[Mrows * Dm];
__device__ float g_enc[Bx * Dm];

__device__ __nv_bfloat16 g_qkvh[Mrows * 3 * Dm], g_qkvl[Mrows * 3 * Dm];
__device__ __nv_bfloat16 g_hh[Mrows * Dm],  g_hl[Mrows * Dm];
__device__ __nv_bfloat16 g_oh[Mrows * Dm],  g_ol[Mrows * Dm];
__device__ __nv_bfloat16 g_fh[Mrows * DFF], g_fl[Mrows * DFF];

#define NQKV (NL * 3 * Dm * Dm)
#define NOUT (NL * Dm * Dm)
#define NFC1 (NL * DFF * Dm)
#define NFC2 (NL * Dm * DFF)
__device__ __nv_bfloat16 g_wqkv_h[NQKV], g_wqkv_l[NQKV];
__device__ __nv_bfloat16 g_wout_h[NOUT], g_wout_l[NOUT];
__device__ __nv_bfloat16 g_wfc1_h[NFC1], g_wfc1_l[NFC1];
__device__ __nv_bfloat16 g_wfc2_h[NFC2], g_wfc2_l[NFC2];

// ---------------- helpers ----------------
__device__ __forceinline__ void split_bf16(float x, __nv_bfloat16& h, __nv_bfloat16& l) {
    h = __float2bfloat16_rn(x);
    l = __float2bfloat16_rn(x - __bfloat162float(h));
}
__device__ __forceinline__ uint32_t sw128(uint32_t o) { return o ^ ((o >> 3) & 0x70); }
__device__ __forceinline__ uint32_t smem_u32(const void* p) {
    return (uint32_t)__cvta_generic_to_shared(p);
}
__device__ __forceinline__ void cp16(uint32_t dst, const void* src) {
    asm volatile("cp.async.cg.shared.global [%0], [%1], 16;" :: "r"(dst), "l"(src));
}
__device__ __forceinline__ void ldmx4(uint32_t* r, uint32_t addr) {
    asm volatile("ldmatrix.sync.aligned.m8n8.x4.shared.b16 {%0,%1,%2,%3}, [%4];"
                 : "=r"(r[0]), "=r"(r[1]), "=r"(r[2]), "=r"(r[3]) : "r"(addr));
}
__device__ __forceinline__ void ldmx4t(uint32_t* r, uint32_t addr) {
    asm volatile("ldmatrix.sync.aligned.m8n8.x4.trans.shared.b16 {%0,%1,%2,%3}, [%4];"
                 : "=r"(r[0]), "=r"(r[1]), "=r"(r[2]), "=r"(r[3]) : "r"(addr));
}
__device__ __forceinline__ void mma16(float* c, const uint32_t* a, const uint32_t* b) {
    asm volatile("mma.sync.aligned.m16n8k16.row.col.f32.bf16.bf16.f32 "
                 "{%0,%1,%2,%3}, {%4,%5,%6,%7}, {%8,%9}, {%0,%1,%2,%3};"
                 : "+f"(c[0]), "+f"(c[1]), "+f"(c[2]), "+f"(c[3])
                 : "r"(a[0]), "r"(a[1]), "r"(a[2]), "r"(a[3]),
                   "r"(b[0]), "r"(b[1]));
}

// ---------------- weight split (vectorized x4) ----------------
__global__ void split_kernel(const float* __restrict__ src,
                             __nv_bfloat16* __restrict__ hi,
                             __nv_bfloat16* __restrict__ lo, int n) {
    int i = (blockIdx.x * 256 + threadIdx.x) * 4;
    if (i >= n) return;
    float4 v = *(const float4*)(src + i);
    __nv_bfloat16 h0, l0, h1, l1, h2, l2, h3, l3;
    split_bf16(v.x, h0, l0); split_bf16(v.y, h1, l1);
    split_bf16(v.z, h2, l2); split_bf16(v.w, h3, l3);
    ushort4 hv, lv;
    hv.x = *(uint16_t*)&h0; hv.y = *(uint16_t*)&h1; hv.z = *(uint16_t*)&h2; hv.w = *(uint16_t*)&h3;
    lv.x = *(uint16_t*)&l0; lv.y = *(uint16_t*)&l1; lv.z = *(uint16_t*)&l2; lv.w = *(uint16_t*)&l3;
    *(ushort4*)(hi + i) = hv;
    *(ushort4*)(lo + i) = lv;
}

// ---------------- patch embed + positional ----------------
__global__ void patch_embed_kernel(const float* __restrict__ x,
                                   const float* __restrict__ pp_w,
                                   const float* __restrict__ pp_b,
                                   const float* __restrict__ pe,
                                   float* __restrict__ z) {
    int idx = blockIdx.x * blockDim.x + threadIdx.x;
    if (idx >= Mrows * Dm) return;
    int row = idx / Dm;
    int d   = idx - row * Dm;
    int b = row >> 9;
    int n = row & 511;
    const float* xr = x + (size_t)b * Tlen + n * PATCH;
    const float* wr = pp_w + (size_t)d * PATCH;
    float s = pp_b[d];
#pragma unroll
    for (int p = 0; p < PATCH; ++p) s += xr[p] * wr[p];
    z[idx] = s + pe[(size_t)n * Dm + d];
}

// ---------------- LayerNorm: warp per row ----------------
template<int OUT>
__global__ __launch_bounds__(256)
void ln_kernel(const float* __restrict__ X,
               const float* __restrict__ gam,
               const float* __restrict__ bet,
               float* __restrict__ Yf,
               __nv_bfloat16* __restrict__ Yh,
               __nv_bfloat16* __restrict__ Yl) {
    const int warp = threadIdx.x >> 5, lane = threadIdx.x & 31;
    const int row = blockIdx.x * 8 + warp;
    const float4* xr = (const float4*)(X + (size_t)row * Dm);
    float4 v[6];
    float s = 0.f;
#pragma unroll
    for (int k = 0; k < 6; ++k) {
        v[k] = xr[lane + 32 * k];
        s += v[k].x + v[k].y + v[k].z + v[k].w;
    }
#pragma unroll
    for (int off = 16; off > 0; off >>= 1) s += __shfl_xor_sync(0xFFFFFFFFu, s, off);
    const float mean = s * (1.0f / Dm);
    float var = 0.f;
#pragma unroll
    for (int k = 0; k < 6; ++k) {
        float a = v[k].x - mean, b = v[k].y - mean, c = v[k].z - mean, d = v[k].w - mean;
        var += a * a + b * b + c * c + d * d;
    }
#pragma unroll
    for (int off = 16; off > 0; off >>= 1) var += __shfl_xor_sync(0xFFFFFFFFu, var, off);
    const float rstd = rsqrtf(var * (1.0f / Dm) + 1e-5f);

#pragma unroll
    for (int k = 0; k < 6; ++k) {
        int j4 = lane + 32 * k;
        float4 g = ((const float4*)gam)[j4];
        float4 b = ((const float4*)bet)[j4];
        float y0 = (v[k].x - mean) * rstd * g.x + b.x;
        float y1 = (v[k].y - mean) * rstd * g.y + b.y;
        float y2 = (v[k].z - mean) * rstd * g.z + b.z;
        float y3 = (v[k].w - mean) * rstd * g.w + b.w;
        if (OUT == 0) {
            ((float4*)(Yf + (size_t)row * Dm))[j4] = make_float4(y0, y1, y2, y3);
        } else {
            __nv_bfloat16 h0, l0, h1, l1, h2, l2, h3, l3;
            split_bf16(y0, h0, l0); split_bf16(y1, h1, l1);
            split_bf16(y2, h2, l2); split_bf16(y3, h3, l3);
            ushort4 hv, lv;
            hv.x = *(uint16_t*)&h0; hv.y = *(uint16_t*)&h1;
            hv.z = *(uint16_t*)&h2; hv.w = *(uint16_t*)&h3;
            lv.x = *(uint16_t*)&l0; lv.y = *(uint16_t*)&l1;
            lv.z = *(uint16_t*)&l2; lv.w = *(uint16_t*)&l3;
            ((ushort4*)(Yh + (size_t)row * Dm))[j4] = hv;
            ((ushort4*)(Yl + (size_t)row * Dm))[j4] = lv;
        }
    }
}

// ---------------- bf16x3 mma.sync GEMM, KTILE=64, 3 stages ----------------
// EPI: 0 fp32; 1 fp32 Res+AB; 2 gelu->(hi,lo); 3 plain ->(hi,lo)
#define KTILE 64
#define ST_OP 16384
#define STG (4 * ST_OP)
#define NSTAGE 3
#define GEMM_SMEM (NSTAGE * STG + 1024)

template<int EPI>
__global__ __launch_bounds__(256, 1)
void wgemm(const __nv_bfloat16* __restrict__ Ah, const __nv_bfloat16* __restrict__ Al,
           const __nv_bfloat16* __restrict__ Wh, const __nv_bfloat16* __restrict__ Wl,
           const float* __restrict__ Res, float* __restrict__ Cf,
           __nv_bfloat16* __restrict__ Chi, __nv_bfloat16* __restrict__ Clo,
           int Nn, int K) {
    extern __shared__ char dyn_smem[];
    const int tid = threadIdx.x, lane = tid & 31, wid = tid >> 5;
    const int warpM = wid & 1, warpN = wid >> 1;
    uint32_t raw = smem_u32(dyn_smem);
    uint32_t sb0 = (raw + 1023u) & ~1023u;

    const int mBase = blockIdx.y * 128, nBase = blockIdx.x * 128;
    const int KT = K >> 6;

    uint32_t swl[4];
    const __nv_bfloat16 *pAh[4], *pAl[4], *pWh[4], *pWl[4];
#pragma unroll
    for (int i = 0; i < 4; ++i) {
        int q = tid + i * 256;
        int row = q >> 3, c = q & 7;
        swl[i] = sw128((uint32_t)(row * 128 + c * 16));
        size_t ga = (size_t)(mBase + row) * K + c * 8;
        size_t gw = (size_t)(nBase + row) * K + c * 8;
        pAh[i] = Ah + ga; pAl[i] = Al + ga;
        pWh[i] = Wh + gw; pWl[i] = Wl + gw;
    }

    float acc[4][4][4];
#pragma unroll
    for (int i = 0; i < 4; ++i)
#pragma unroll
        for (int j = 0; j < 4; ++j)
#pragma unroll
            for (int q = 0; q < 4; ++q) acc[i][j][q] = 0.f;

#define LOADSTG(kt)                                                              \
    do {                                                                         \
        const int kofs_ = (kt) * KTILE;                                          \
        const uint32_t sb_ = sb0 + ((kt) % NSTAGE) * STG;                        \
        _Pragma("unroll")                                                        \
        for (int i_ = 0; i_ < 4; ++i_) {                                         \
            cp16(sb_ + swl[i_],              pAh[i_] + kofs_);                   \
            cp16(sb_ + ST_OP + swl[i_],      pAl[i_] + kofs_);                   \
            cp16(sb_ + 2 * ST_OP + swl[i_],  pWh[i_] + kofs_);                   \
            cp16(sb_ + 3 * ST_OP + swl[i_],  pWl[i_] + kofs_);                   \
        }                                                                        \
        asm volatile("cp.async.commit_group;" ::: "memory");                     \
    } while (0)

    LOADSTG(0);
    LOADSTG(1);

    const int arow = warpM * 64 + (lane & 15);
    const int akb  = (lane >> 4) << 4;
    const int bprow = warpN * 32 + ((lane >> 4) & 1) * 8 + (lane & 7);
    const int bpkb  = ((lane >> 3) & 1) << 4;

    for (int kt = 0; kt < KT; ++kt) {
        if (kt + 1 < KT) {
            asm volatile("cp.async.wait_group 1;" ::: "memory");
        } else {
            asm volatile("cp.async.wait_group 0;" ::: "memory");
        }
        __syncthreads();
        if (kt + 2 < KT) LOADSTG(kt + 2);

        const uint32_t A0 = sb0 + (kt % NSTAGE) * STG;
        const uint32_t W0 = A0 + 2 * ST_OP;

#pragma unroll
        for (int kc = 0; kc < 4; ++kc) {
            uint32_t ah[4][4], al[4][4];
#pragma unroll
            for (int i = 0; i < 4; ++i) {
                uint32_t off = sw128((uint32_t)((arow + i * 16) * 128 + kc * 32 + akb));
                ldmx4(ah[i], A0 + off);
                ldmx4(al[i], A0 + ST_OP + off);
            }
            uint32_t bh[4][2], bl[4][2];
#pragma unroll
            for (int jp = 0; jp < 2; ++jp) {
                uint32_t off = sw128((uint32_t)((bprow + jp * 16) * 128 + kc * 32 + bpkb));
                uint32_t r[4];
                ldmx4(r, W0 + off);
                bh[2 * jp][0] = r[0]; bh[2 * jp][1] = r[1];
                bh[2 * jp + 1][0] = r[2]; bh[2 * jp + 1][1] = r[3];
                ldmx4(r, W0 + ST_OP + off);
                bl[2 * jp][0] = r[0]; bl[2 * jp][1] = r[1];
                bl[2 * jp + 1][0] = r[2]; bl[2 * jp + 1][1] = r[3];
            }
#pragma unroll
            for (int i = 0; i < 4; ++i)
#pragma unroll
                for (int j = 0; j < 4; ++j) {
                    mma16(acc[i][j], ah[i], bh[j]);
                    mma16(acc[i][j], ah[i], bl[j]);
                    mma16(acc[i][j], al[i], bh[j]);
                }
        }
    }

    const int erow = warpM * 64 + (lane >> 2);
    const int ecol = warpN * 32 + (lane & 3) * 2;
#pragma unroll
    for (int i = 0; i < 4; ++i) {
        int row0 = mBase + erow + i * 16;
#pragma unroll
        for (int j = 0; j < 4; ++j) {
            int col = nBase + ecol + j * 8;
            size_t g0 = (size_t)row0 * Nn + col;
            size_t g1 = g0 + (size_t)8 * Nn;
            float v0 = acc[i][j][0], v1 = acc[i][j][1];
            float v2 = acc[i][j][2], v3 = acc[i][j][3];
            if (EPI == 0) {
                *(float2*)(Cf + g0) = make_float2(v0, v1);
                *(float2*)(Cf + g1) = make_float2(v2, v3);
            } else if (EPI == 1) {
                float2 r0 = *(const float2*)(Res + g0);
                float2 r1 = *(const float2*)(Res + g1);
                *(float2*)(Cf + g0) = make_float2(v0 + r0.x, v1 + r0.y);
                *(float2*)(Cf + g1) = make_float2(v2 + r1.x, v3 + r1.y);
            } else {
                if (EPI == 2) {
                    v0 = 0.5f * v0 * (1.0f + erff(v0 * 0.70710678118654752f));
                    v1 = 0.5f * v1 * (1.0f + erff(v1 * 0.70710678118654752f));
                    v2 = 0.5f * v2 * (1.0f + erff(v2 * 0.70710678118654752f));
                    v3 = 0.5f * v3 * (1.0f + erff(v3 * 0.70710678118654752f));
                }
                __nv_bfloat16 h0, l0, h1, l1, h2, l2, h3, l3;
                split_bf16(v0, h0, l0); split_bf16(v1, h1, l1);
                split_bf16(v2, h2, l2); split_bf16(v3, h3, l3);
                *(__nv_bfloat162*)(Chi + g0) = __nv_bfloat162(h0, h1);
                *(__nv_bfloat162*)(Clo + g0) = __nv_bfloat162(l0, l1);
                *(__nv_bfloat162*)(Chi + g1) = __nv_bfloat162(h2, h3);
                *(__nv_bfloat162*)(Clo + g1) = __nv_bfloat162(l2, l3);
            }
        }
    }
}

// ---------------- causal attention v7: warp-mma + double-buffered K/V ----------------
// CTA = (b, h, 64 queries), 4 warps. smem: 2 buffers x (KH KL VH VL) = 64KB.
// Q staged in buffer 1 (KH/KL slots) initially; extracted to regs before buf1 reuse.
#define A_BUF(t) ((t) * 32768)
#define A_KH 0
#define A_KL 8192
#define A_VH 16384
#define A_VL 24576
#define A_QH (A_BUF(1) + 0)
#define A_QL (A_BUF(1) + 8192)
#define ATT_SMEM 65536

__global__ __launch_bounds__(128)
void attn_kernel(const __nv_bfloat16* __restrict__ qkvh,
                 const __nv_bfloat16* __restrict__ qkvl,
                 __nv_bfloat16* __restrict__ ohi, __nv_bfloat16* __restrict__ olo) {
    extern __shared__ char asm_[];
    const uint32_t sb = smem_u32(asm_);
    const int b = blockIdx.z, h = blockIdx.y;
    const int qb = gridDim.x - 1 - blockIdx.x;   // heavy first
    const int tid = threadIdx.x, lane = tid & 31, w = tid >> 5;
    const int qBase = qb * 64;

    // loader chunk coords
#define KVLOAD(c, base)                                                              \
    do {                                                                             \
        _Pragma("unroll")                                                            \
        for (int i_ = 0; i_ < 4; ++i_) {                                             \
            int q_ = tid + i_ * 128;                                                 \
            int row_ = q_ >> 3, cc_ = q_ & 7;                                        \
            uint32_t sw_ = sw128((uint32_t)(row_ * 128 + cc_ * 16));                 \
            size_t gk_ = (size_t)(b * Ntok + (c) * 64 + row_) * (3 * Dm) + Dm + h * HD + cc_ * 8; \
            cp16(sb + (base) + A_KH + sw_, qkvh + gk_);                              \
            cp16(sb + (base) + A_KL + sw_, qkvl + gk_);                              \
            cp16(sb + (base) + A_VH + sw_, qkvh + gk_ + Dm);                         \
            cp16(sb + (base) + A_VL + sw_, qkvl + gk_ + Dm);                         \
        }                                                                            \
        asm volatile("cp.async.commit_group;" ::: "memory");                         \
    } while (0)

    // initial: Q into buf1 slots + chunk0 into buf0, one group
    {
#pragma unroll
        for (int i = 0; i < 4; ++i) {
            int q = tid + i * 128;
            int row = q >> 3, c = q & 7;
            uint32_t sw = sw128((uint32_t)(row * 128 + c * 16));
            size_t gq = (size_t)(b * Ntok + qBase + row) * (3 * Dm) + h * HD + c * 8;
            cp16(sb + A_QH + sw, qkvh + gq);
            cp16(sb + A_QL + sw, qkvl + gq);
        }
        KVLOAD(0, A_BUF(0));
        asm volatile("cp.async.wait_group 0;" ::: "memory");
        __syncthreads();
    }

    // Q fragments -> registers (before buf1 is ever overwritten)
    uint32_t qh[4][4], ql[4][4];
    {
        const int arow = w * 16 + (lane & 15);
        const int akb  = (lane >> 4) << 4;
#pragma unroll
        for (int kc = 0; kc < 4; ++kc) {
            uint32_t off = sw128((uint32_t)(arow * 128 + kc * 32 + akb));
            ldmx4(qh[kc], sb + A_QH + off);
            ldmx4(ql[kc], sb + A_QL + off);
        }
    }

    float oacc[8][4];
#pragma unroll
    for (int n = 0; n < 8; ++n)
#pragma unroll
        for (int q = 0; q < 4; ++q) oacc[n][q] = 0.f;
    float M0 = -INFINITY, M1 = -INFINITY, Sum0 = 0.f, Sum1 = 0.f;

    const int row0 = qBase + w * 16 + (lane >> 2);
    const int row1 = row0 + 8;
    const int colq = (lane & 3) * 2;

    const int bprow = ((lane >> 4) & 1) * 8 + (lane & 7);
    const int bpkb  = ((lane >> 3) & 1) << 4;
    const int vrow = lane & 15;
    const int vcb  = (lane & 16) ? 16 : 0;

    for (int c = 0; c <= qb; ++c) {
        const uint32_t B0 = sb + A_BUF(c & 1);
        if (c + 1 <= qb) {
            __syncthreads();                    // all warps done with buf[(c+1)&1]
            KVLOAD(c + 1, A_BUF((c + 1) & 1));
            asm volatile("cp.async.wait_group 1;" ::: "memory");  // chunk c done
        } else {
            asm volatile("cp.async.wait_group 0;" ::: "memory");
        }
        __syncthreads();

        // ---- S = Q K^T (3-pass) ----
        float sacc[8][4];
#pragma unroll
        for (int n = 0; n < 8; ++n)
#pragma unroll
            for (int q = 0; q < 4; ++q) sacc[n][q] = 0.f;

#pragma unroll
        for (int kc = 0; kc < 4; ++kc) {
            uint32_t kh[8][2], kl[8][2];
#pragma unroll
            for (int p = 0; p < 4; ++p) {
                uint32_t off = sw128((uint32_t)((p * 16 + bprow) * 128 + kc * 32 + bpkb));
                uint32_t r[4];
                ldmx4(r, B0 + A_KH + off);
                kh[2 * p][0] = r[0]; kh[2 * p][1] = r[1];
                kh[2 * p + 1][0] = r[2]; kh[2 * p + 1][1] = r[3];
                ldmx4(r, B0 + A_KL + off);
                kl[2 * p][0] = r[0]; kl[2 * p][1] = r[1];
                kl[2 * p + 1][0] = r[2]; kl[2 * p + 1][1] = r[3];
            }
#pragma unroll
            for (int n = 0; n < 8; ++n) {
                mma16(sacc[n], qh[kc], kh[n]);
                mma16(sacc[n], qh[kc], kl[n]);
                mma16(sacc[n], ql[kc], kh[n]);
            }
        }

        // ---- scale + causal mask ----
        const int kb = c * 64 + colq;
#pragma unroll
        for (int n = 0; n < 8; ++n) {
            int k0 = kb + n * 8, k1 = k0 + 1;
            sacc[n][0] = (k0 > row0) ? -INFINITY : sacc[n][0] * 0.125f;
            sacc[n][1] = (k1 > row0) ? -INFINITY : sacc[n][1] * 0.125f;
            sacc[n][2] = (k0 > row1) ? -INFINITY : sacc[n][2] * 0.125f;
            sacc[n][3] = (k1 > row1) ? -INFINITY : sacc[n][3] * 0.125f;
        }

        // ---- online softmax ----
        float rm0 = -INFINITY, rm1 = -INFINITY;
#pragma unroll
        for (int n = 0; n < 8; ++n) {
            rm0 = fmaxf(rm0, fmaxf(sacc[n][0], sacc[n][1]));
            rm1 = fmaxf(rm1, fmaxf(sacc[n][2], sacc[n][3]));
        }
        rm0 = fmaxf(rm0, __shfl_xor_sync(0xFFFFFFFFu, rm0, 1));
        rm0 = fmaxf(rm0, __shfl_xor_sync(0xFFFFFFFFu, rm0, 2));
        rm1 = fmaxf(rm1, __shfl_xor_sync(0xFFFFFFFFu, rm1, 1));
        rm1 = fmaxf(rm1, __shfl_xor_sync(0xFFFFFFFFu, rm1, 2));
        float nM0 = fmaxf(M0, rm0), nM1 = fmaxf(M1, rm1);
        float sc0 = __expf(M0 - nM0), sc1 = __expf(M1 - nM1);
        float rs0 = 0.f, rs1 = 0.f;
#pragma unroll
        for (int n = 0; n < 8; ++n) {
            float p0 = (sacc[n][0] == -INFINITY) ? 0.f : __expf(sacc[n][0] - nM0);
            float p1 = (sacc[n][1] == -INFINITY) ? 0.f : __expf(sacc[n][1] - nM0);
            float p2 = (sacc[n][2] == -INFINITY) ? 0.f : __expf(sacc[n][2] - nM1);
            float p3 = (sacc[n][3] == -INFINITY) ? 0.f : __expf(sacc[n][3] - nM1);
            sacc[n][0] = p0; sacc[n][1] = p1; sacc[n][2] = p2; sacc[n][3] = p3;
            rs0 += p0 + p1; rs1 += p2 + p3;
        }
        rs0 += __shfl_xor_sync(0xFFFFFFFFu, rs0, 1);
        rs0 += __shfl_xor_sync(0xFFFFFFFFu, rs0, 2);
        rs1 += __shfl_xor_sync(0xFFFFFFFFu, rs1, 1);
        rs1 += __shfl_xor_sync(0xFFFFFFFFu, rs1, 2);
        Sum0 = Sum0 * sc0 + rs0; Sum1 = Sum1 * sc1 + rs1;
        M0 = nM0; M1 = nM1;
#pragma unroll
        for (int n = 0; n < 8; ++n) {
            oacc[n][0] *= sc0; oacc[n][1] *= sc0;
            oacc[n][2] *= sc1; oacc[n][3] *= sc1;
        }

        // ---- P hi/lo fragments ----
        uint32_t ph[4][4], pl[4][4];
#pragma unroll
        for (int s = 0; s < 4; ++s) {
#pragma unroll
            for (int half = 0; half < 2; ++half) {
                int t = 2 * s + half;
                float v0 = sacc[t][0], v1 = sacc[t][1], v2 = sacc[t][2], v3 = sacc[t][3];
                __nv_bfloat16 h0, l0, h1, l1, h2, l2, h3, l3;
                split_bf16(v0, h0, l0); split_bf16(v1, h1, l1);
                split_bf16(v2, h2, l2); split_bf16(v3, h3, l3);
                __nv_bfloat162 ph01(h0, h1), ph23(h2, h3), pl01(l0, l1), pl23(l2, l3);
                ph[s][2 * half + 0] = *(uint32_t*)&ph01;
                ph[s][2 * half + 1] = *(uint32_t*)&ph23;
                pl[s][2 * half + 0] = *(uint32_t*)&pl01;
                pl[s][2 * half + 1] = *(uint32_t*)&pl23;
            }
        }

        // ---- O += P V (3-pass) ----
#pragma unroll
        for (int s = 0; s < 4; ++s) {
            uint32_t vh[8][2], vl[8][2];
#pragma unroll
            for (int p = 0; p < 4; ++p) {
                uint32_t off = sw128((uint32_t)((s * 16 + vrow) * 128 + p * 32 + vcb));
                uint32_t r[4];
                ldmx4t(r, B0 + A_VH + off);
                vh[2 * p][0] = r[0]; vh[2 * p][1] = r[1];
                vh[2 * p + 1][0] = r[2]; vh[2 * p + 1][1] = r[3];
                ldmx4t(r, B0 + A_VL + off);
                vl[2 * p][0] = r[0]; vl[2 * p][1] = r[1];
                vl[2 * p + 1][0] = r[2]; vl[2 * p + 1][1] = r[3];
            }
#pragma unroll
            for (int n = 0; n < 8; ++n) {
                mma16(oacc[n], ph[s], vh[n]);
                mma16(oacc[n], ph[s], vl[n]);
                mma16(oacc[n], pl[s], vh[n]);
            }
        }
    }

    // ---- finalize + split store ----
    const float inv0 = 1.0f / Sum0, inv1 = 1.0f / Sum1;
    const size_t tok0 = (size_t)(b * Ntok + row0) * Dm + h * HD;
    const size_t tok1 = (size_t)(b * Ntok + row1) * Dm + h * HD;
#pragma unroll
    for (int n = 0; n < 8; ++n) {
        int d = n * 8 + colq;
        float v0 = oacc[n][0] * inv0, v1 = oacc[n][1] * inv0;
        float v2 = oacc[n][2] * inv1, v3 = oacc[n][3] * inv1;
        __nv_bfloat16 h0, l0, h1, l1, h2, l2, h3, l3;
        split_bf16(v0, h0, l0); split_bf16(v1, h1, l1);
        split_bf16(v2, h2, l2); split_bf16(v3, h3, l3);
        *(__nv_bfloat162*)(ohi + tok0 + d) = __nv_bfloat162(h0, h1);
        *(__nv_bfloat162*)(olo + tok0 + d) = __nv_bfloat162(l0, l1);
        *(__nv_bfloat162*)(ohi + tok1 + d) = __nv_bfloat162(h2, h3);
        *(__nv_bfloat162*)(olo + tok1 + d) = __nv_bfloat162(l2, l3);
    }
}

// ---------------- final mean over tokens ----------------
__global__ void mean_kernel(const float* __restrict__ hln, float* __restrict__ enc) {
    int idx = blockIdx.x * blockDim.x + threadIdx.x;
    if (idx >= Bx * Dm) return;
    int b = idx / Dm, d = idx - b * Dm;
    float s = 0.f;
    const float* base = hln + (size_t)b * Ntok * Dm + d;
    for (int n = 0; n < Ntok; ++n) s += base[(size_t)n * Dm];
    enc[idx] = s * (1.0f / Ntok);
}

// ---------------- head ----------------
__global__ void head_kernel(const float* __restrict__ enc,
                            const float* __restrict__ h1w, const float* __restrict__ h1b,
                            const float* __restrict__ h2w, const float* __restrict__ h2b,
                            float* __restrict__ out) {
    __shared__ float es[Dm];
    __shared__ float ys[Dm / 2];
    int b = blockIdx.x, tid = threadIdx.x;
    for (int j = tid; j < Dm; j += blockDim.x) es[j] = enc[(size_t)b * Dm + j];
    __syncthreads();
    int j = tid;
    float s = h1b[j];
    const float* wr = h1w + (size_t)j * Dm;
#pragma unroll 4
    for (int d = 0; d < Dm; ++d) s = fmaf(es[d], wr[d], s);
    ys[j] = fmaxf(s, 0.f);
    __syncthreads();
    if (tid < 2) {
        float s2 = h2b[tid];
        const float* w2 = h2w + (size_t)tid * (Dm / 2);
        for (int q = 0; q < Dm / 2; ++q) s2 = fmaf(ys[q], w2[q], s2);
        out[b * 2 + tid] = s2;
    }
}

// ---------------- launch ----------------
extern "C" void kernel_launch(void* const* d_in, const int* in_sizes, int n_in,
                              void* d_out, int out_size) {
    const float* x     = (const float*)d_in[0];
    const float* pp_w  = (const float*)d_in[1];
    const float* pp_b  = (const float*)d_in[2];
    const float* pe    = (const float*)d_in[3];
    const float* ln1_g = (const float*)d_in[4];
    const float* ln1_b = (const float*)d_in[5];
    const float* qkv_w = (const float*)d_in[6];
    const float* out_w = (const float*)d_in[7];
    const float* ln2_g = (const float*)d_in[8];
    const float* ln2_b = (const float*)d_in[9];
    const float* fc1_w = (const float*)d_in[10];
    const float* fc2_w = (const float*)d_in[11];
    const float* lnf_g = (const float*)d_in[12];
    const float* lnf_b = (const float*)d_in[13];
    const float* h1_w  = (const float*)d_in[14];
    const float* h1_b  = (const float*)d_in[15];
    const float* h2_w  = (const float*)d_in[16];
    const float* h2_b  = (const float*)d_in[17];

    float *z, *h, *enc;
    __nv_bfloat16 *qvh, *qvl, *hh, *hl, *oh, *ol, *fh, *fl;
    __nv_bfloat16 *wqh, *wql, *woh, *wol, *w1h, *w1l, *w2h, *w2l;
    cudaGetSymbolAddress((void**)&z,   g_z);
    cudaGetSymbolAddress((void**)&h,   g_h);
    cudaGetSymbolAddress((void**)&enc, g_enc);
    cudaGetSymbolAddress((void**)&qvh, g_qkvh); cudaGetSymbolAddress((void**)&qvl, g_qkvl);
    cudaGetSymbolAddress((void**)&hh,  g_hh);  cudaGetSymbolAddress((void**)&hl, g_hl);
    cudaGetSymbolAddress((void**)&oh,  g_oh);  cudaGetSymbolAddress((void**)&ol, g_ol);
    cudaGetSymbolAddress((void**)&fh,  g_fh);  cudaGetSymbolAddress((void**)&fl, g_fl);
    cudaGetSymbolAddress((void**)&wqh, g_wqkv_h); cudaGetSymbolAddress((void**)&wql, g_wqkv_l);
    cudaGetSymbolAddress((void**)&woh, g_wout_h); cudaGetSymbolAddress((void**)&wol, g_wout_l);
    cudaGetSymbolAddress((void**)&w1h, g_wfc1_h); cudaGetSymbolAddress((void**)&w1l, g_wfc1_l);
    cudaGetSymbolAddress((void**)&w2h, g_wfc2_h); cudaGetSymbolAddress((void**)&w2l, g_wfc2_l);

    cudaFuncSetAttribute(wgemm<0>, cudaFuncAttributeMaxDynamicSharedMemorySize, GEMM_SMEM);
    cudaFuncSetAttribute(wgemm<1>, cudaFuncAttributeMaxDynamicSharedMemorySize, GEMM_SMEM);
    cudaFuncSetAttribute(wgemm<2>, cudaFuncAttributeMaxDynamicSharedMemorySize, GEMM_SMEM);
    cudaFuncSetAttribute(wgemm<3>, cudaFuncAttributeMaxDynamicSharedMemorySize, GEMM_SMEM);
    cudaFuncSetAttribute(attn_kernel, cudaFuncAttributeMaxDynamicSharedMemorySize, ATT_SMEM);

    split_kernel<<<NQKV / 1024, 256>>>(qkv_w, wqh, wql, NQKV);
    split_kernel<<<NOUT / 1024, 256>>>(out_w, woh, wol, NOUT);
    split_kernel<<<NFC1 / 1024, 256>>>(fc1_w, w1h, w1l, NFC1);
    split_kernel<<<NFC2 / 1024, 256>>>(fc2_w, w2h, w2l, NFC2);

    patch_embed_kernel<<<(Mrows * Dm + 255) / 256, 256>>>(x, pp_w, pp_b, pe, z);

    for (int i = 0; i < NL; ++i) {
        ln_kernel<1><<<Mrows / 8, 256>>>(z, ln1_g + i * Dm, ln1_b + i * Dm, nullptr, hh, hl);
        wgemm<3><<<dim3((3 * Dm) / 128, Mrows / 128), 256, GEMM_SMEM>>>(
            hh, hl, wqh + (size_t)i * 3 * Dm * Dm, wql + (size_t)i * 3 * Dm * Dm,
            nullptr, nullptr, qvh, qvl, 3 * Dm, Dm);
        attn_kernel<<<dim3(Ntok / 64, Hh, Bx), 128, ATT_SMEM>>>(qvh, qvl, oh, ol);
        wgemm<1><<<dim3(Dm / 128, Mrows / 128), 256, GEMM_SMEM>>>(
            oh, ol, woh + (size_t)i * Dm * Dm, wol + (size_t)i * Dm * Dm,
            z, z, nullptr, nullptr, Dm, Dm);
        ln_kernel<1><<<Mrows / 8, 256>>>(z, ln2_g + i * Dm, ln2_b + i * Dm, nullptr, hh, hl);
        wgemm<2><<<dim3(DFF / 128, Mrows / 128), 256, GEMM_SMEM>>>(
            hh, hl, w1h + (size_t)i * DFF * Dm, w1l + (size_t)i * DFF * Dm,
            nullptr, nullptr, fh, fl, DFF, Dm);
        wgemm<1><<<dim3(Dm / 128, Mrows / 128), 256, GEMM_SMEM>>>(
            fh, fl, w2h + (size_t)i * Dm * DFF, w2l + (size_t)i * Dm * DFF,
            z, z, nullptr, nullptr, Dm, DFF);
    }

    ln_kernel<0><<<Mrows / 8, 256>>>(z, lnf_g, lnf_b, h, nullptr, nullptr);
    mean_kernel<<<(Bx * Dm + 255) / 256, 256>>>(h, enc);
    head_kernel<<<Bx, Dm / 2>>>(enc, h1_w, h1_b, h2_w, h2_b, (float*)d_out);
}

// round 17
// speedup vs baseline: 1.2639x; 1.0868x over previous
#include <cuda_runtime.h>
#include <cuda_bf16.h>
#include <cstdint>
#include <math.h>

#define Bx 8
#define Ntok 512
#define Dm 768
#define Hh 12
#define HD 64
#define NL 6
#define DFF 3072
#define Mrows (Bx * Ntok)      // 4096
#define Tlen 8192
#define PATCH 16

// ---------------- scratch (device globals; no allocation) ----------------
__device__ float g_z[Mrows * Dm];
__device__ float g_h[Mrows * Dm];
__device__ float g_enc[Bx * Dm];
__device__ float g_pk[2 * Mrows * Dm];     // split-K partials

__device__ __nv_bfloat16 g_qkvh[Mrows * 3 * Dm], g_qkvl[Mrows * 3 * Dm];
__device__ __nv_bfloat16 g_hh[Mrows * Dm],  g_hl[Mrows * Dm];
__device__ __nv_bfloat16 g_oh[Mrows * Dm],  g_ol[Mrows * Dm];
__device__ __nv_bfloat16 g_fh[Mrows * DFF], g_fl[Mrows * DFF];

#define NQKV (NL * 3 * Dm * Dm)
#define NOUT (NL * Dm * Dm)
#define NFC1 (NL * DFF * Dm)
#define NFC2 (NL * Dm * DFF)
__device__ __nv_bfloat16 g_wqkv_h[NQKV], g_wqkv_l[NQKV];
__device__ __nv_bfloat16 g_wout_h[NOUT], g_wout_l[NOUT];
__device__ __nv_bfloat16 g_wfc1_h[NFC1], g_wfc1_l[NFC1];
__device__ __nv_bfloat16 g_wfc2_h[NFC2], g_wfc2_l[NFC2];

// ---------------- helpers ----------------
__device__ __forceinline__ void split_bf16(float x, __nv_bfloat16& h, __nv_bfloat16& l) {
    h = __float2bfloat16_rn(x);
    l = __float2bfloat16_rn(x - __bfloat162float(h));
}
__device__ __forceinline__ uint32_t sw128(uint32_t o) { return o ^ ((o >> 3) & 0x70); }
__device__ __forceinline__ uint32_t smem_u32(const void* p) {
    return (uint32_t)__cvta_generic_to_shared(p);
}
__device__ __forceinline__ void cp16(uint32_t dst, const void* src) {
    asm volatile("cp.async.cg.shared.global [%0], [%1], 16;" :: "r"(dst), "l"(src));
}
__device__ __forceinline__ void ldmx4(uint32_t* r, uint32_t addr) {
    asm volatile("ldmatrix.sync.aligned.m8n8.x4.shared.b16 {%0,%1,%2,%3}, [%4];"
                 : "=r"(r[0]), "=r"(r[1]), "=r"(r[2]), "=r"(r[3]) : "r"(addr));
}
__device__ __forceinline__ void ldmx4t(uint32_t* r, uint32_t addr) {
    asm volatile("ldmatrix.sync.aligned.m8n8.x4.trans.shared.b16 {%0,%1,%2,%3}, [%4];"
                 : "=r"(r[0]), "=r"(r[1]), "=r"(r[2]), "=r"(r[3]) : "r"(addr));
}
__device__ __forceinline__ void mma16(float* c, const uint32_t* a, const uint32_t* b) {
    asm volatile("mma.sync.aligned.m16n8k16.row.col.f32.bf16.bf16.f32 "
                 "{%0,%1,%2,%3}, {%4,%5,%6,%7}, {%8,%9}, {%0,%1,%2,%3};"
                 : "+f"(c[0]), "+f"(c[1]), "+f"(c[2]), "+f"(c[3])
                 : "r"(a[0]), "r"(a[1]), "r"(a[2]), "r"(a[3]),
                   "r"(b[0]), "r"(b[1]));
}

// ---------------- weight split (vectorized x4) ----------------
__global__ void split_kernel(const float* __restrict__ src,
                             __nv_bfloat16* __restrict__ hi,
                             __nv_bfloat16* __restrict__ lo, int n) {
    int i = (blockIdx.x * 256 + threadIdx.x) * 4;
    if (i >= n) return;
    float4 v = *(const float4*)(src + i);
    __nv_bfloat16 h0, l0, h1, l1, h2, l2, h3, l3;
    split_bf16(v.x, h0, l0); split_bf16(v.y, h1, l1);
    split_bf16(v.z, h2, l2); split_bf16(v.w, h3, l3);
    ushort4 hv, lv;
    hv.x = *(uint16_t*)&h0; hv.y = *(uint16_t*)&h1; hv.z = *(uint16_t*)&h2; hv.w = *(uint16_t*)&h3;
    lv.x = *(uint16_t*)&l0; lv.y = *(uint16_t*)&l1; lv.z = *(uint16_t*)&l2; lv.w = *(uint16_t*)&l3;
    *(ushort4*)(hi + i) = hv;
    *(ushort4*)(lo + i) = lv;
}

// ---------------- patch embed + positional ----------------
__global__ void patch_embed_kernel(const float* __restrict__ x,
                                   const float* __restrict__ pp_w,
                                   const float* __restrict__ pp_b,
                                   const float* __restrict__ pe,
                                   float* __restrict__ z) {
    int idx = blockIdx.x * blockDim.x + threadIdx.x;
    if (idx >= Mrows * Dm) return;
    int row = idx / Dm;
    int d   = idx - row * Dm;
    int b = row >> 9;
    int n = row & 511;
    const float* xr = x + (size_t)b * Tlen + n * PATCH;
    const float* wr = pp_w + (size_t)d * PATCH;
    float s = pp_b[d];
#pragma unroll
    for (int p = 0; p < PATCH; ++p) s += xr[p] * wr[p];
    z[idx] = s + pe[(size_t)n * Dm + d];
}

// ---------------- split-K reduction: z += P0 + P1 ----------------
__global__ void addred_kernel(float* __restrict__ z, const float* __restrict__ p) {
    int i = (blockIdx.x * 256 + threadIdx.x) * 4;
    float4 a = *(const float4*)(z + i);
    float4 b = *(const float4*)(p + i);
    float4 c = *(const float4*)(p + i + (size_t)Mrows * Dm);
    *(float4*)(z + i) = make_float4(a.x + b.x + c.x, a.y + b.y + c.y,
                                    a.z + b.z + c.z, a.w + b.w + c.w);
}

// ---------------- LayerNorm: warp per row ----------------
template<int OUT>
__global__ __launch_bounds__(256)
void ln_kernel(const float* __restrict__ X,
               const float* __restrict__ gam,
               const float* __restrict__ bet,
               float* __restrict__ Yf,
               __nv_bfloat16* __restrict__ Yh,
               __nv_bfloat16* __restrict__ Yl) {
    const int warp = threadIdx.x >> 5, lane = threadIdx.x & 31;
    const int row = blockIdx.x * 8 + warp;
    const float4* xr = (const float4*)(X + (size_t)row * Dm);
    float4 v[6];
    float s = 0.f;
#pragma unroll
    for (int k = 0; k < 6; ++k) {
        v[k] = xr[lane + 32 * k];
        s += v[k].x + v[k].y + v[k].z + v[k].w;
    }
#pragma unroll
    for (int off = 16; off > 0; off >>= 1) s += __shfl_xor_sync(0xFFFFFFFFu, s, off);
    const float mean = s * (1.0f / Dm);
    float var = 0.f;
#pragma unroll
    for (int k = 0; k < 6; ++k) {
        float a = v[k].x - mean, b = v[k].y - mean, c = v[k].z - mean, d = v[k].w - mean;
        var += a * a + b * b + c * c + d * d;
    }
#pragma unroll
    for (int off = 16; off > 0; off >>= 1) var += __shfl_xor_sync(0xFFFFFFFFu, var, off);
    const float rstd = rsqrtf(var * (1.0f / Dm) + 1e-5f);

#pragma unroll
    for (int k = 0; k < 6; ++k) {
        int j4 = lane + 32 * k;
        float4 g = ((const float4*)gam)[j4];
        float4 b = ((const float4*)bet)[j4];
        float y0 = (v[k].x - mean) * rstd * g.x + b.x;
        float y1 = (v[k].y - mean) * rstd * g.y + b.y;
        float y2 = (v[k].z - mean) * rstd * g.z + b.z;
        float y3 = (v[k].w - mean) * rstd * g.w + b.w;
        if (OUT == 0) {
            ((float4*)(Yf + (size_t)row * Dm))[j4] = make_float4(y0, y1, y2, y3);
        } else {
            __nv_bfloat16 h0, l0, h1, l1, h2, l2, h3, l3;
            split_bf16(y0, h0, l0); split_bf16(y1, h1, l1);
            split_bf16(y2, h2, l2); split_bf16(y3, h3, l3);
            ushort4 hv, lv;
            hv.x = *(uint16_t*)&h0; hv.y = *(uint16_t*)&h1;
            hv.z = *(uint16_t*)&h2; hv.w = *(uint16_t*)&h3;
            lv.x = *(uint16_t*)&l0; lv.y = *(uint16_t*)&l1;
            lv.z = *(uint16_t*)&l2; lv.w = *(uint16_t*)&l3;
            ((ushort4*)(Yh + (size_t)row * Dm))[j4] = hv;
            ((ushort4*)(Yl + (size_t)row * Dm))[j4] = lv;
        }
    }
}

// ---------------- bf16x3 mma.sync GEMM, KTILE=64, 3 stages ----------------
// EPI: 0 fp32 (+ blockIdx.z partial offset); 1 fp32 Res+AB; 2 gelu->(hi,lo); 3 plain ->(hi,lo)
// lda = row stride of A/W in elements; K = this CTA's K extent; blockIdx.z = K-split index.
#define KTILE 64
#define ST_OP 16384
#define STG (4 * ST_OP)
#define NSTAGE 3
#define GEMM_SMEM (NSTAGE * STG + 1024)

template<int EPI>
__global__ __launch_bounds__(256, 1)
void wgemm(const __nv_bfloat16* __restrict__ Ah, const __nv_bfloat16* __restrict__ Al,
           const __nv_bfloat16* __restrict__ Wh, const __nv_bfloat16* __restrict__ Wl,
           const float* __restrict__ Res, float* __restrict__ Cf,
           __nv_bfloat16* __restrict__ Chi, __nv_bfloat16* __restrict__ Clo,
           int Nn, int K, int lda) {
    extern __shared__ char dyn_smem[];
    const int tid = threadIdx.x, lane = tid & 31, wid = tid >> 5;
    const int warpM = wid & 1, warpN = wid >> 1;
    uint32_t raw = smem_u32(dyn_smem);
    uint32_t sb0 = (raw + 1023u) & ~1023u;

    const int mBase = blockIdx.y * 128, nBase = blockIdx.x * 128;
    const int koff = blockIdx.z * K;
    const int KT = K >> 6;

    uint32_t swl[4];
    const __nv_bfloat16 *pAh[4], *pAl[4], *pWh[4], *pWl[4];
#pragma unroll
    for (int i = 0; i < 4; ++i) {
        int q = tid + i * 256;
        int row = q >> 3, c = q & 7;
        swl[i] = sw128((uint32_t)(row * 128 + c * 16));
        size_t ga = (size_t)(mBase + row) * lda + koff + c * 8;
        size_t gw = (size_t)(nBase + row) * lda + koff + c * 8;
        pAh[i] = Ah + ga; pAl[i] = Al + ga;
        pWh[i] = Wh + gw; pWl[i] = Wl + gw;
    }

    float acc[4][4][4];
#pragma unroll
    for (int i = 0; i < 4; ++i)
#pragma unroll
        for (int j = 0; j < 4; ++j)
#pragma unroll
            for (int q = 0; q < 4; ++q) acc[i][j][q] = 0.f;

#define LOADSTG(kt)                                                              \
    do {                                                                         \
        const int kofs_ = (kt) * KTILE;                                          \
        const uint32_t sb_ = sb0 + ((kt) % NSTAGE) * STG;                        \
        _Pragma("unroll")                                                        \
        for (int i_ = 0; i_ < 4; ++i_) {                                         \
            cp16(sb_ + swl[i_],              pAh[i_] + kofs_);                   \
            cp16(sb_ + ST_OP + swl[i_],      pAl[i_] + kofs_);                   \
            cp16(sb_ + 2 * ST_OP + swl[i_],  pWh[i_] + kofs_);                   \
            cp16(sb_ + 3 * ST_OP + swl[i_],  pWl[i_] + kofs_);                   \
        }                                                                        \
        asm volatile("cp.async.commit_group;" ::: "memory");                     \
    } while (0)

    LOADSTG(0);
    LOADSTG(1);

    const int arow = warpM * 64 + (lane & 15);
    const int akb  = (lane >> 4) << 4;
    const int bprow = warpN * 32 + ((lane >> 4) & 1) * 8 + (lane & 7);
    const int bpkb  = ((lane >> 3) & 1) << 4;

    for (int kt = 0; kt < KT; ++kt) {
        if (kt + 1 < KT) {
            asm volatile("cp.async.wait_group 1;" ::: "memory");
        } else {
            asm volatile("cp.async.wait_group 0;" ::: "memory");
        }
        __syncthreads();
        if (kt + 2 < KT) LOADSTG(kt + 2);

        const uint32_t A0 = sb0 + (kt % NSTAGE) * STG;
        const uint32_t W0 = A0 + 2 * ST_OP;

#pragma unroll
        for (int kc = 0; kc < 4; ++kc) {
            uint32_t ah[4][4], al[4][4];
#pragma unroll
            for (int i = 0; i < 4; ++i) {
                uint32_t off = sw128((uint32_t)((arow + i * 16) * 128 + kc * 32 + akb));
                ldmx4(ah[i], A0 + off);
                ldmx4(al[i], A0 + ST_OP + off);
            }
            uint32_t bh[4][2], bl[4][2];
#pragma unroll
            for (int jp = 0; jp < 2; ++jp) {
                uint32_t off = sw128((uint32_t)((bprow + jp * 16) * 128 + kc * 32 + bpkb));
                uint32_t r[4];
                ldmx4(r, W0 + off);
                bh[2 * jp][0] = r[0]; bh[2 * jp][1] = r[1];
                bh[2 * jp + 1][0] = r[2]; bh[2 * jp + 1][1] = r[3];
                ldmx4(r, W0 + ST_OP + off);
                bl[2 * jp][0] = r[0]; bl[2 * jp][1] = r[1];
                bl[2 * jp + 1][0] = r[2]; bl[2 * jp + 1][1] = r[3];
            }
#pragma unroll
            for (int i = 0; i < 4; ++i)
#pragma unroll
                for (int j = 0; j < 4; ++j) {
                    mma16(acc[i][j], ah[i], bh[j]);
                    mma16(acc[i][j], ah[i], bl[j]);
                    mma16(acc[i][j], al[i], bh[j]);
                }
        }
    }

    float* Cfz = Cf + (size_t)blockIdx.z * Mrows * Nn;   // partial slab for split-K
    const int erow = warpM * 64 + (lane >> 2);
    const int ecol = warpN * 32 + (lane & 3) * 2;
#pragma unroll
    for (int i = 0; i < 4; ++i) {
        int row0 = mBase + erow + i * 16;
#pragma unroll
        for (int j = 0; j < 4; ++j) {
            int col = nBase + ecol + j * 8;
            size_t g0 = (size_t)row0 * Nn + col;
            size_t g1 = g0 + (size_t)8 * Nn;
            float v0 = acc[i][j][0], v1 = acc[i][j][1];
            float v2 = acc[i][j][2], v3 = acc[i][j][3];
            if (EPI == 0) {
                *(float2*)(Cfz + g0) = make_float2(v0, v1);
                *(float2*)(Cfz + g1) = make_float2(v2, v3);
            } else if (EPI == 1) {
                float2 r0 = *(const float2*)(Res + g0);
                float2 r1 = *(const float2*)(Res + g1);
                *(float2*)(Cf + g0) = make_float2(v0 + r0.x, v1 + r0.y);
                *(float2*)(Cf + g1) = make_float2(v2 + r1.x, v3 + r1.y);
            } else {
                if (EPI == 2) {
                    v0 = 0.5f * v0 * (1.0f + erff(v0 * 0.70710678118654752f));
                    v1 = 0.5f * v1 * (1.0f + erff(v1 * 0.70710678118654752f));
                    v2 = 0.5f * v2 * (1.0f + erff(v2 * 0.70710678118654752f));
                    v3 = 0.5f * v3 * (1.0f + erff(v3 * 0.70710678118654752f));
                }
                __nv_bfloat16 h0, l0, h1, l1, h2, l2, h3, l3;
                split_bf16(v0, h0, l0); split_bf16(v1, h1, l1);
                split_bf16(v2, h2, l2); split_bf16(v3, h3, l3);
                *(__nv_bfloat162*)(Chi + g0) = __nv_bfloat162(h0, h1);
                *(__nv_bfloat162*)(Clo + g0) = __nv_bfloat162(l0, l1);
                *(__nv_bfloat162*)(Chi + g1) = __nv_bfloat162(h2, h3);
                *(__nv_bfloat162*)(Clo + g1) = __nv_bfloat162(l2, l3);
            }
        }
    }
}

// ---------------- causal attention v7: warp-mma + double-buffered K/V ----------------
#define A_BUF(t) ((t) * 32768)
#define A_KH 0
#define A_KL 8192
#define A_VH 16384
#define A_VL 24576
#define A_QH (A_BUF(1) + 0)
#define A_QL (A_BUF(1) + 8192)
#define ATT_SMEM 65536

__global__ __launch_bounds__(128)
void attn_kernel(const __nv_bfloat16* __restrict__ qkvh,
                 const __nv_bfloat16* __restrict__ qkvl,
                 __nv_bfloat16* __restrict__ ohi, __nv_bfloat16* __restrict__ olo) {
    extern __shared__ char asm_[];
    const uint32_t sb = smem_u32(asm_);
    const int b = blockIdx.z, h = blockIdx.y;
    const int qb = gridDim.x - 1 - blockIdx.x;
    const int tid = threadIdx.x, lane = tid & 31, w = tid >> 5;
    const int qBase = qb * 64;

#define KVLOAD(c, base)                                                              \
    do {                                                                             \
        _Pragma("unroll")                                                            \
        for (int i_ = 0; i_ < 4; ++i_) {                                             \
            int q_ = tid + i_ * 128;                                                 \
            int row_ = q_ >> 3, cc_ = q_ & 7;                                        \
            uint32_t sw_ = sw128((uint32_t)(row_ * 128 + cc_ * 16));                 \
            size_t gk_ = (size_t)(b * Ntok + (c) * 64 + row_) * (3 * Dm) + Dm + h * HD + cc_ * 8; \
            cp16(sb + (base) + A_KH + sw_, qkvh + gk_);                              \
            cp16(sb + (base) + A_KL + sw_, qkvl + gk_);                              \
            cp16(sb + (base) + A_VH + sw_, qkvh + gk_ + Dm);                         \
            cp16(sb + (base) + A_VL + sw_, qkvl + gk_ + Dm);                         \
        }                                                                            \
        asm volatile("cp.async.commit_group;" ::: "memory");                         \
    } while (0)

    {
#pragma unroll
        for (int i = 0; i < 4; ++i) {
            int q = tid + i * 128;
            int row = q >> 3, c = q & 7;
            uint32_t sw = sw128((uint32_t)(row * 128 + c * 16));
            size_t gq = (size_t)(b * Ntok + qBase + row) * (3 * Dm) + h * HD + c * 8;
            cp16(sb + A_QH + sw, qkvh + gq);
            cp16(sb + A_QL + sw, qkvl + gq);
        }
        KVLOAD(0, A_BUF(0));
        asm volatile("cp.async.wait_group 0;" ::: "memory");
        __syncthreads();
    }

    uint32_t qh[4][4], ql[4][4];
    {
        const int arow = w * 16 + (lane & 15);
        const int akb  = (lane >> 4) << 4;
#pragma unroll
        for (int kc = 0; kc < 4; ++kc) {
            uint32_t off = sw128((uint32_t)(arow * 128 + kc * 32 + akb));
            ldmx4(qh[kc], sb + A_QH + off);
            ldmx4(ql[kc], sb + A_QL + off);
        }
    }

    float oacc[8][4];
#pragma unroll
    for (int n = 0; n < 8; ++n)
#pragma unroll
        for (int q = 0; q < 4; ++q) oacc[n][q] = 0.f;
    float M0 = -INFINITY, M1 = -INFINITY, Sum0 = 0.f, Sum1 = 0.f;

    const int row0 = qBase + w * 16 + (lane >> 2);
    const int row1 = row0 + 8;
    const int colq = (lane & 3) * 2;

    const int bprow = ((lane >> 4) & 1) * 8 + (lane & 7);
    const int bpkb  = ((lane >> 3) & 1) << 4;
    const int vrow = lane & 15;
    const int vcb  = (lane & 16) ? 16 : 0;

    for (int c = 0; c <= qb; ++c) {
        const uint32_t B0 = sb + A_BUF(c & 1);
        if (c + 1 <= qb) {
            __syncthreads();
            KVLOAD(c + 1, A_BUF((c + 1) & 1));
            asm volatile("cp.async.wait_group 1;" ::: "memory");
        } else {
            asm volatile("cp.async.wait_group 0;" ::: "memory");
        }
        __syncthreads();

        float sacc[8][4];
#pragma unroll
        for (int n = 0; n < 8; ++n)
#pragma unroll
            for (int q = 0; q < 4; ++q) sacc[n][q] = 0.f;

#pragma unroll
        for (int kc = 0; kc < 4; ++kc) {
            uint32_t kh[8][2], kl[8][2];
#pragma unroll
            for (int p = 0; p < 4; ++p) {
                uint32_t off = sw128((uint32_t)((p * 16 + bprow) * 128 + kc * 32 + bpkb));
                uint32_t r[4];
                ldmx4(r, B0 + A_KH + off);
                kh[2 * p][0] = r[0]; kh[2 * p][1] = r[1];
                kh[2 * p + 1][0] = r[2]; kh[2 * p + 1][1] = r[3];
                ldmx4(r, B0 + A_KL + off);
                kl[2 * p][0] = r[0]; kl[2 * p][1] = r[1];
                kl[2 * p + 1][0] = r[2]; kl[2 * p + 1][1] = r[3];
            }
#pragma unroll
            for (int n = 0; n < 8; ++n) {
                mma16(sacc[n], qh[kc], kh[n]);
                mma16(sacc[n], qh[kc], kl[n]);
                mma16(sacc[n], ql[kc], kh[n]);
            }
        }

        const int kb = c * 64 + colq;
#pragma unroll
        for (int n = 0; n < 8; ++n) {
            int k0 = kb + n * 8, k1 = k0 + 1;
            sacc[n][0] = (k0 > row0) ? -INFINITY : sacc[n][0] * 0.125f;
            sacc[n][1] = (k1 > row0) ? -INFINITY : sacc[n][1] * 0.125f;
            sacc[n][2] = (k0 > row1) ? -INFINITY : sacc[n][2] * 0.125f;
            sacc[n][3] = (k1 > row1) ? -INFINITY : sacc[n][3] * 0.125f;
        }

        float rm0 = -INFINITY, rm1 = -INFINITY;
#pragma unroll
        for (int n = 0; n < 8; ++n) {
            rm0 = fmaxf(rm0, fmaxf(sacc[n][0], sacc[n][1]));
            rm1 = fmaxf(rm1, fmaxf(sacc[n][2], sacc[n][3]));
        }
        rm0 = fmaxf(rm0, __shfl_xor_sync(0xFFFFFFFFu, rm0, 1));
        rm0 = fmaxf(rm0, __shfl_xor_sync(0xFFFFFFFFu, rm0, 2));
        rm1 = fmaxf(rm1, __shfl_xor_sync(0xFFFFFFFFu, rm1, 1));
        rm1 = fmaxf(rm1, __shfl_xor_sync(0xFFFFFFFFu, rm1, 2));
        float nM0 = fmaxf(M0, rm0), nM1 = fmaxf(M1, rm1);
        float sc0 = __expf(M0 - nM0), sc1 = __expf(M1 - nM1);
        float rs0 = 0.f, rs1 = 0.f;
#pragma unroll
        for (int n = 0; n < 8; ++n) {
            float p0 = (sacc[n][0] == -INFINITY) ? 0.f : __expf(sacc[n][0] - nM0);
            float p1 = (sacc[n][1] == -INFINITY) ? 0.f : __expf(sacc[n][1] - nM0);
            float p2 = (sacc[n][2] == -INFINITY) ? 0.f : __expf(sacc[n][2] - nM1);
            float p3 = (sacc[n][3] == -INFINITY) ? 0.f : __expf(sacc[n][3] - nM1);
            sacc[n][0] = p0; sacc[n][1] = p1; sacc[n][2] = p2; sacc[n][3] = p3;
            rs0 += p0 + p1; rs1 += p2 + p3;
        }
        rs0 += __shfl_xor_sync(0xFFFFFFFFu, rs0, 1);
        rs0 += __shfl_xor_sync(0xFFFFFFFFu, rs0, 2);
        rs1 += __shfl_xor_sync(0xFFFFFFFFu, rs1, 1);
        rs1 += __shfl_xor_sync(0xFFFFFFFFu, rs1, 2);
        Sum0 = Sum0 * sc0 + rs0; Sum1 = Sum1 * sc1 + rs1;
        M0 = nM0; M1 = nM1;
#pragma unroll
        for (int n = 0; n < 8; ++n) {
            oacc[n][0] *= sc0; oacc[n][1] *= sc0;
            oacc[n][2] *= sc1; oacc[n][3] *= sc1;
        }

        uint32_t ph[4][4], pl[4][4];
#pragma unroll
        for (int s = 0; s < 4; ++s) {
#pragma unroll
            for (int half = 0; half < 2; ++half) {
                int t = 2 * s + half;
                float v0 = sacc[t][0], v1 = sacc[t][1], v2 = sacc[t][2], v3 = sacc[t][3];
                __nv_bfloat16 h0, l0, h1, l1, h2, l2, h3, l3;
                split_bf16(v0, h0, l0); split_bf16(v1, h1, l1);
                split_bf16(v2, h2, l2); split_bf16(v3, h3, l3);
                __nv_bfloat162 ph01(h0, h1), ph23(h2, h3), pl01(l0, l1), pl23(l2, l3);
                ph[s][2 * half + 0] = *(uint32_t*)&ph01;
                ph[s][2 * half + 1] = *(uint32_t*)&ph23;
                pl[s][2 * half + 0] = *(uint32_t*)&pl01;
                pl[s][2 * half + 1] = *(uint32_t*)&pl23;
            }
        }

#pragma unroll
        for (int s = 0; s < 4; ++s) {
            uint32_t vh[8][2], vl[8][2];
#pragma unroll
            for (int p = 0; p < 4; ++p) {
                uint32_t off = sw128((uint32_t)((s * 16 + vrow) * 128 + p * 32 + vcb));
                uint32_t r[4];
                ldmx4t(r, B0 + A_VH + off);
                vh[2 * p][0] = r[0]; vh[2 * p][1] = r[1];
                vh[2 * p + 1][0] = r[2]; vh[2 * p + 1][1] = r[3];
                ldmx4t(r, B0 + A_VL + off);
                vl[2 * p][0] = r[0]; vl[2 * p][1] = r[1];
                vl[2 * p + 1][0] = r[2]; vl[2 * p + 1][1] = r[3];
            }
#pragma unroll
            for (int n = 0; n < 8; ++n) {
                mma16(oacc[n], ph[s], vh[n]);
                mma16(oacc[n], ph[s], vl[n]);
                mma16(oacc[n], pl[s], vh[n]);
            }
        }
    }

    const float inv0 = 1.0f / Sum0, inv1 = 1.0f / Sum1;
    const size_t tok0 = (size_t)(b * Ntok + row0) * Dm + h * HD;
    const size_t tok1 = (size_t)(b * Ntok + row1) * Dm + h * HD;
#pragma unroll
    for (int n = 0; n < 8; ++n) {
        int d = n * 8 + colq;
        float v0 = oacc[n][0] * inv0, v1 = oacc[n][1] * inv0;
        float v2 = oacc[n][2] * inv1, v3 = oacc[n][3] * inv1;
        __nv_bfloat16 h0, l0, h1, l1, h2, l2, h3, l3;
        split_bf16(v0, h0, l0); split_bf16(v1, h1, l1);
        split_bf16(v2, h2, l2); split_bf16(v3, h3, l3);
        *(__nv_bfloat162*)(ohi + tok0 + d) = __nv_bfloat162(h0, h1);
        *(__nv_bfloat162*)(olo + tok0 + d) = __nv_bfloat162(l0, l1);
        *(__nv_bfloat162*)(ohi + tok1 + d) = __nv_bfloat162(h2, h3);
        *(__nv_bfloat162*)(olo + tok1 + d) = __nv_bfloat162(l2, l3);
    }
}

// ---------------- final mean over tokens ----------------
__global__ void mean_kernel(const float* __restrict__ hln, float* __restrict__ enc) {
    int idx = blockIdx.x * blockDim.x + threadIdx.x;
    if (idx >= Bx * Dm) return;
    int b = idx / Dm, d = idx - b * Dm;
    float s = 0.f;
    const float* base = hln + (size_t)b * Ntok * Dm + d;
    for (int n = 0; n < Ntok; ++n) s += base[(size_t)n * Dm];
    enc[idx] = s * (1.0f / Ntok);
}

// ---------------- head ----------------
__global__ void head_kernel(const float* __restrict__ enc,
                            const float* __restrict__ h1w, const float* __restrict__ h1b,
                            const float* __restrict__ h2w, const float* __restrict__ h2b,
                            float* __restrict__ out) {
    __shared__ float es[Dm];
    __shared__ float ys[Dm / 2];
    int b = blockIdx.x, tid = threadIdx.x;
    for (int j = tid; j < Dm; j += blockDim.x) es[j] = enc[(size_t)b * Dm + j];
    __syncthreads();
    int j = tid;
    float s = h1b[j];
    const float* wr = h1w + (size_t)j * Dm;
#pragma unroll 4
    for (int d = 0; d < Dm; ++d) s = fmaf(es[d], wr[d], s);
    ys[j] = fmaxf(s, 0.f);
    __syncthreads();
    if (tid < 2) {
        float s2 = h2b[tid];
        const float* w2 = h2w + (size_t)tid * (Dm / 2);
        for (int q = 0; q < Dm / 2; ++q) s2 = fmaf(ys[q], w2[q], s2);
        out[b * 2 + tid] = s2;
    }
}

// ---------------- launch ----------------
extern "C" void kernel_launch(void* const* d_in, const int* in_sizes, int n_in,
                              void* d_out, int out_size) {
    const float* x     = (const float*)d_in[0];
    const float* pp_w  = (const float*)d_in[1];
    const float* pp_b  = (const float*)d_in[2];
    const float* pe    = (const float*)d_in[3];
    const float* ln1_g = (const float*)d_in[4];
    const float* ln1_b = (const float*)d_in[5];
    const float* qkv_w = (const float*)d_in[6];
    const float* out_w = (const float*)d_in[7];
    const float* ln2_g = (const float*)d_in[8];
    const float* ln2_b = (const float*)d_in[9];
    const float* fc1_w = (const float*)d_in[10];
    const float* fc2_w = (const float*)d_in[11];
    const float* lnf_g = (const float*)d_in[12];
    const float* lnf_b = (const float*)d_in[13];
    const float* h1_w  = (const float*)d_in[14];
    const float* h1_b  = (const float*)d_in[15];
    const float* h2_w  = (const float*)d_in[16];
    const float* h2_b  = (const float*)d_in[17];

    float *z, *h, *enc, *pk;
    __nv_bfloat16 *qvh, *qvl, *hh, *hl, *oh, *ol, *fh, *fl;
    __nv_bfloat16 *wqh, *wql, *woh, *wol, *w1h, *w1l, *w2h, *w2l;
    cudaGetSymbolAddress((void**)&z,   g_z);
    cudaGetSymbolAddress((void**)&h,   g_h);
    cudaGetSymbolAddress((void**)&enc, g_enc);
    cudaGetSymbolAddress((void**)&pk,  g_pk);
    cudaGetSymbolAddress((void**)&qvh, g_qkvh); cudaGetSymbolAddress((void**)&qvl, g_qkvl);
    cudaGetSymbolAddress((void**)&hh,  g_hh);  cudaGetSymbolAddress((void**)&hl, g_hl);
    cudaGetSymbolAddress((void**)&oh,  g_oh);  cudaGetSymbolAddress((void**)&ol, g_ol);
    cudaGetSymbolAddress((void**)&fh,  g_fh);  cudaGetSymbolAddress((void**)&fl, g_fl);
    cudaGetSymbolAddress((void**)&wqh, g_wqkv_h); cudaGetSymbolAddress((void**)&wql, g_wqkv_l);
    cudaGetSymbolAddress((void**)&woh, g_wout_h); cudaGetSymbolAddress((void**)&wol, g_wout_l);
    cudaGetSymbolAddress((void**)&w1h, g_wfc1_h); cudaGetSymbolAddress((void**)&w1l, g_wfc1_l);
    cudaGetSymbolAddress((void**)&w2h, g_wfc2_h); cudaGetSymbolAddress((void**)&w2l, g_wfc2_l);

    cudaFuncSetAttribute(wgemm<0>, cudaFuncAttributeMaxDynamicSharedMemorySize, GEMM_SMEM);
    cudaFuncSetAttribute(wgemm<1>, cudaFuncAttributeMaxDynamicSharedMemorySize, GEMM_SMEM);
    cudaFuncSetAttribute(wgemm<2>, cudaFuncAttributeMaxDynamicSharedMemorySize, GEMM_SMEM);
    cudaFuncSetAttribute(wgemm<3>, cudaFuncAttributeMaxDynamicSharedMemorySize, GEMM_SMEM);
    cudaFuncSetAttribute(attn_kernel, cudaFuncAttributeMaxDynamicSharedMemorySize, ATT_SMEM);

    split_kernel<<<NQKV / 1024, 256>>>(qkv_w, wqh, wql, NQKV);
    split_kernel<<<NOUT / 1024, 256>>>(out_w, woh, wol, NOUT);
    split_kernel<<<NFC1 / 1024, 256>>>(fc1_w, w1h, w1l, NFC1);
    split_kernel<<<NFC2 / 1024, 256>>>(fc2_w, w2h, w2l, NFC2);

    patch_embed_kernel<<<(Mrows * Dm + 255) / 256, 256>>>(x, pp_w, pp_b, pe, z);

    const int ADDR_GRID = (Mrows * Dm) / 1024;

    for (int i = 0; i < NL; ++i) {
        ln_kernel<1><<<Mrows / 8, 256>>>(z, ln1_g + i * Dm, ln1_b + i * Dm, nullptr, hh, hl);
        wgemm<3><<<dim3((3 * Dm) / 128, Mrows / 128), 256, GEMM_SMEM>>>(
            hh, hl, wqh + (size_t)i * 3 * Dm * Dm, wql + (size_t)i * 3 * Dm * Dm,
            nullptr, nullptr, qvh, qvl, 3 * Dm, Dm, Dm);
        attn_kernel<<<dim3(Ntok / 64, Hh, Bx), 128, ATT_SMEM>>>(qvh, qvl, oh, ol);
        // out-proj: split-K2 -> partials, then z += P0 + P1
        wgemm<0><<<dim3(Dm / 128, Mrows / 128, 2), 256, GEMM_SMEM>>>(
            oh, ol, woh + (size_t)i * Dm * Dm, wol + (size_t)i * Dm * Dm,
            nullptr, pk, nullptr, nullptr, Dm, Dm / 2, Dm);
        addred_kernel<<<ADDR_GRID, 256>>>(z, pk);
        ln_kernel<1><<<Mrows / 8, 256>>>(z, ln2_g + i * Dm, ln2_b + i * Dm, nullptr, hh, hl);
        wgemm<2><<<dim3(DFF / 128, Mrows / 128), 256, GEMM_SMEM>>>(
            hh, hl, w1h + (size_t)i * DFF * Dm, w1l + (size_t)i * DFF * Dm,
            nullptr, nullptr, fh, fl, DFF, Dm, Dm);
        // fc2: split-K2 -> partials, then z += P0 + P1
        wgemm<0><<<dim3(Dm / 128, Mrows / 128, 2), 256, GEMM_SMEM>>>(
            fh, fl, w2h + (size_t)i * Dm * DFF, w2l + (size_t)i * Dm * DFF,
            nullptr, pk, nullptr, nullptr, Dm, DFF / 2, DFF);
        addred_kernel<<<ADDR_GRID, 256>>>(z, pk);
    }

    ln_kernel<0><<<Mrows / 8, 256>>>(z, lnf_g, lnf_b, h, nullptr, nullptr);
    mean_kernel<<<(Bx * Dm + 255) / 256, 256>>>(h, enc);
    head_kernel<<<Bx, Dm / 2>>>(enc, h1_w, h1_b, h2_w, h2_b, (float*)d_out);
}